// round 7
// baseline (speedup 1.0000x reference)
#include <cuda_runtime.h>
#include <cuda_fp16.h>
#include <cstdint>

// ----------------------------------------------------------------------------
// B = 8192, K = 512, L = 10752 literals, C = 2688 conj, F = 256
// fp16 mma.sync m16n8k16 GEMM; x@muT folded in as extra N-tiles.
// CTA 128x192, 256 threads (8 warps, warp tile 64x48 => 146 B LDS per HMMA).
// ----------------------------------------------------------------------------
#define BATCH   8192
#define KDIM    512
#define LDIM    10752
#define LDIM2   11136        // + 256 mu rows + 128 zero pad
#define CDIM    2688
#define FDIM    256
#define DPITCH  384

#define BM 128
#define BN 192               // 16 triples = 48 conjunctions (triple-aligned)
#define BK 64
#define NTHREADS 256         // 8 warps: 2 (m) x 4 (n), warp tile 64 x 48
#define STAGE   40960        // (128+192)*128 bytes
#define BOFF    16384
#define SM_BIAS (3 * STAGE)  // 122880
#define SMEM_NEED (SM_BIAS + 1024)
#define LPITCH  200
#define NLT     (LDIM / BN)  // 56 literal tiles; bx 56,57 are mu tiles

// scratch
__device__ __half g_A[(size_t)BATCH * KDIM];
__device__ __half g_B[(size_t)LDIM2 * KDIM];
__device__ float g_conj[(size_t)BATCH * CDIM];
__device__ float g_dot[(size_t)BATCH * DPITCH];
__device__ float g_xn[BATCH];
__device__ float g_mn[FDIM];

// ---------------------------------------------------------------- helpers
__device__ __forceinline__ uint32_t smem_u32(const void* p) {
    uint32_t a;
    asm("{ .reg .u64 t; cvta.to.shared.u64 t, %1; cvt.u32.u64 %0, t; }" : "=r"(a) : "l"(p));
    return a;
}
__device__ __forceinline__ void cp16(uint32_t dst, const void* src) {
    asm volatile("cp.async.cg.shared.global [%0], [%1], 16;" :: "r"(dst), "l"(src) : "memory");
}
#define CP_COMMIT() asm volatile("cp.async.commit_group;" ::: "memory")
#define CP_WAIT(n)  asm volatile("cp.async.wait_group %0;" :: "n"(n) : "memory")

__device__ __forceinline__ void ldsm_x4(uint32_t addr, uint32_t r[4]) {
    asm volatile("ldmatrix.sync.aligned.m8n8.x4.shared.b16 {%0,%1,%2,%3}, [%4];"
        : "=r"(r[0]), "=r"(r[1]), "=r"(r[2]), "=r"(r[3]) : "r"(addr));
}
__device__ __forceinline__ void mma_f16(float c[4], const uint32_t a[4],
                                        uint32_t b0, uint32_t b1) {
    asm volatile("mma.sync.aligned.m16n8k16.row.col.f32.f16.f16.f32 "
        "{%0,%1,%2,%3}, {%4,%5,%6,%7}, {%8,%9}, {%0,%1,%2,%3};"
        : "+f"(c[0]), "+f"(c[1]), "+f"(c[2]), "+f"(c[3])
        : "r"(a[0]), "r"(a[1]), "r"(a[2]), "r"(a[3]), "r"(b0), "r"(b1));
}

__device__ __forceinline__ float fast_tanh(float x) {
    float ax = fabsf(x);
    float t;
    asm("ex2.approx.f32 %0, %1;" : "=f"(t) : "f"(ax * -2.885390082f));
    float r = __fdividef(1.f - t, 1.f + t);
    return copysignf(r, x);
}

// ---------------------------------------------------------------- prep kernels
__global__ void prep_x_kernel(const float* __restrict__ x) {
    int i = blockIdx.x * blockDim.x + threadIdx.x;
    if (i >= BATCH * KDIM / 8) return;
    float4 v0 = *(const float4*)(x + (size_t)i * 8);
    float4 v1 = *(const float4*)(x + (size_t)i * 8 + 4);
    __half2 h[4];
    h[0] = __floats2half2_rn(v0.x, v0.y);
    h[1] = __floats2half2_rn(v0.z, v0.w);
    h[2] = __floats2half2_rn(v1.x, v1.y);
    h[3] = __floats2half2_rn(v1.z, v1.w);
    *(uint4*)(g_A + (size_t)i * 8) = *(uint4*)h;
}

__global__ void prep_w_kernel(const float* __restrict__ w, const float* __restrict__ m) {
    __shared__ float s[32][33];
    int n0 = blockIdx.x * 32, k0 = blockIdx.y * 32;
    int tx = threadIdx.x, ty = threadIdx.y;
    size_t gi = (size_t)(k0 + ty) * LDIM + n0 + tx;
    s[ty][tx] = w[gi] * m[gi];
    __syncthreads();
    g_B[(size_t)(n0 + ty) * KDIM + k0 + tx] = __float2half_rn(s[tx][ty]);
}

__global__ void prep_mu_kernel(const float* __restrict__ mu) {
    const int tid = threadIdx.x, wid = tid >> 5, lane = tid & 31;
    if (blockIdx.x < 32) {
        int f = blockIdx.x * 8 + wid;
        const float* src = mu + (size_t)f * KDIM;
        __half* dst = g_B + (size_t)(LDIM + f) * KDIM;
        float sq = 0.f;
#pragma unroll
        for (int j = 0; j < 4; j++) {
            int idx = lane + j * 32;
            float4 v = *(const float4*)(src + idx * 4);
            sq = fmaf(v.x, v.x, sq); sq = fmaf(v.y, v.y, sq);
            sq = fmaf(v.z, v.z, sq); sq = fmaf(v.w, v.w, sq);
            __half2 h0 = __floats2half2_rn(v.x, v.y);
            __half2 h1 = __floats2half2_rn(v.z, v.w);
            uint2 pk = make_uint2(*(uint32_t*)&h0, *(uint32_t*)&h1);
            *(uint2*)(dst + idx * 4) = pk;
        }
#pragma unroll
        for (int off = 16; off > 0; off >>= 1)
            sq += __shfl_xor_sync(0xffffffffu, sq, off);
        if (lane == 0) g_mn[f] = sq;
    } else {
        int row = LDIM + FDIM + (blockIdx.x - 32) * 8 + wid;
        __half* dst = g_B + (size_t)row * KDIM;
#pragma unroll
        for (int j = 0; j < 4; j++) {
            int idx = lane + j * 32;
            *(uint2*)(dst + idx * 4) = make_uint2(0u, 0u);
        }
    }
}

__global__ void xn_kernel(const float* __restrict__ x) {
    const int tid = threadIdx.x, wid = tid >> 5, lane = tid & 31;
    int row = blockIdx.x * 8 + wid;
    const float* src = x + (size_t)row * KDIM;
    float sq = 0.f;
#pragma unroll
    for (int j = 0; j < 4; j++) {
        int idx = lane + j * 32;
        float4 v = *(const float4*)(src + idx * 4);
        sq = fmaf(v.x, v.x, sq); sq = fmaf(v.y, v.y, sq);
        sq = fmaf(v.z, v.z, sq); sq = fmaf(v.w, v.w, sq);
    }
#pragma unroll
    for (int off = 16; off > 0; off >>= 1)
        sq += __shfl_xor_sync(0xffffffffu, sq, off);
    if (lane == 0) g_xn[row] = sq;
}

// ---------------------------------------------------------------- fused GEMM
__global__ __launch_bounds__(NTHREADS, 1)
void fused_gemm_dnf_kernel(const float* __restrict__ bias) {
    extern __shared__ char smp[];
    const uint32_t sb = smem_u32(smp);

    const int tid = threadIdx.x;
    const int wid = tid >> 5, lane = tid & 31;
    const int bx = blockIdx.x;   // 0..55 literals, 56..57 mu
    const int by = blockIdx.y;
    const int warp_m = wid & 1;  // 2 x 64-row bands
    const int warp_n = wid >> 1; // 4 x 48-col bands

    float* sbias = (float*)(smp + SM_BIAS);
    if (tid < BN && bx < NLT) sbias[tid] = bias[bx * BN + tid];

    const __half* Ag = g_A + (size_t)(by * BM) * KDIM;
    const __half* Bg = g_B + (size_t)(bx * BN) * KDIM;

    const int r16 = lane & 15, l4 = lane >> 4;
    int am128[4], a7[4];
#pragma unroll
    for (int t = 0; t < 4; t++) {
        int row = warp_m * 64 + t * 16 + r16;
        am128[t] = row * 128; a7[t] = row & 7;
    }
    int bn128[3], b7[3];
#pragma unroll
    for (int i = 0; i < 3; i++) {
        int n = warp_n * 48 + i * 16 + r16;
        bn128[i] = n * 128; b7[i] = n & 7;
    }

    float c[4][6][4];
#pragma unroll
    for (int t = 0; t < 4; t++)
#pragma unroll
        for (int n = 0; n < 6; n++)
#pragma unroll
            for (int e = 0; e < 4; e++) c[t][n][e] = 0.f;

    // A: 128 rows x 8 chunks = 1024 ops (4/thread); B: 192 x 8 = 1536 (6/thread)
#define ISSUE(kt)                                                              \
    {                                                                          \
        const uint32_t stA = sb + ((kt) % 3) * STAGE;                          \
        _Pragma("unroll")                                                      \
        for (int j = 0; j < 4; j++) {                                          \
            int idx = tid + NTHREADS * j;                                      \
            int row = idx >> 3, ch = idx & 7;                                  \
            cp16(stA + row * 128 + ((ch ^ (row & 7)) << 4),                    \
                 Ag + (size_t)row * KDIM + (kt) * BK + ch * 8);                \
        }                                                                      \
        _Pragma("unroll")                                                      \
        for (int j = 0; j < 6; j++) {                                          \
            int idx = tid + NTHREADS * j;                                      \
            int row = idx >> 3, ch = idx & 7;                                  \
            cp16(stA + BOFF + row * 128 + ((ch ^ (row & 7)) << 4),             \
                 Bg + (size_t)row * KDIM + (kt) * BK + ch * 8);                \
        }                                                                      \
        CP_COMMIT();                                                           \
    }

    ISSUE(0);
    ISSUE(1);

    const int NKT = KDIM / BK;   // 8
    for (int kt = 0; kt < NKT; kt++) {
        CP_WAIT(1);
        __syncthreads();
        if (kt + 2 < NKT) { ISSUE(kt + 2); } else { CP_COMMIT(); }

        const uint32_t sA = sb + (kt % 3) * STAGE;
        const uint32_t sB = sA + BOFF;
#pragma unroll
        for (int ks = 0; ks < 4; ks++) {
            uint32_t af[4][4], bf[3][4];
            const int ch = 2 * ks + l4;
#pragma unroll
            for (int t = 0; t < 4; t++)
                ldsm_x4(sA + am128[t] + ((ch ^ a7[t]) << 4), af[t]);
#pragma unroll
            for (int i = 0; i < 3; i++)
                ldsm_x4(sB + bn128[i] + ((ch ^ b7[i]) << 4), bf[i]);
#pragma unroll
            for (int t = 0; t < 4; t++)
#pragma unroll
                for (int i = 0; i < 3; i++) {
                    mma_f16(c[t][2 * i + 0], af[t], bf[i][0], bf[i][2]);
                    mma_f16(c[t][2 * i + 1], af[t], bf[i][1], bf[i][3]);
                }
        }
    }
#undef ISSUE

    CP_WAIT(0);
    __syncthreads();

    const int g = lane >> 2, cc = lane & 3;

    if (bx >= NLT) {
        // ------------- mu tiles: write raw dots to g_dot -------------
        const int colbase = bx * BN - LDIM;   // 0 or 192
        float* dp = g_dot + (size_t)(by * BM) * DPITCH + colbase;
#pragma unroll
        for (int t = 0; t < 4; t++) {
            int row0 = warp_m * 64 + t * 16 + g;
#pragma unroll
            for (int i = 0; i < 3; i++)
#pragma unroll
                for (int j = 0; j < 2; j++) {
                    int colb = warp_n * 48 + i * 16 + j * 8 + 2 * cc;
                    int nt = 2 * i + j;
                    *(float2*)(dp + (size_t)row0 * DPITCH + colb) =
                        make_float2(c[t][nt][0], c[t][nt][1]);
                    *(float2*)(dp + (size_t)(row0 + 8) * DPITCH + colb) =
                        make_float2(c[t][nt][2], c[t][nt][3]);
                }
        }
        return;
    }

    // ---------------- literal epilogue: tanh + conj reduce ----------------
    float* Ls = (float*)smp;   // [128][LPITCH]
#pragma unroll
    for (int t = 0; t < 4; t++) {
        int row0 = warp_m * 64 + t * 16 + g;
#pragma unroll
        for (int i = 0; i < 3; i++)
#pragma unroll
            for (int j = 0; j < 2; j++) {
                int colb = warp_n * 48 + i * 16 + j * 8 + 2 * cc;
                int nt = 2 * i + j;
                float b0 = sbias[colb], b1 = sbias[colb + 1];
                float2 v0, v1;
                v0.x = fast_tanh(c[t][nt][0] + b0);
                v0.y = fast_tanh(c[t][nt][1] + b1);
                v1.x = fast_tanh(c[t][nt][2] + b0);
                v1.y = fast_tanh(c[t][nt][3] + b1);
                *(float2*)(Ls + row0 * LPITCH + colb) = v0;
                *(float2*)(Ls + (row0 + 8) * LPITCH + colb) = v1;
            }
    }
    __syncthreads();

    // 128 rows x 48 conj = 6144 tasks
    for (int t = tid; t < BM * 48; t += NTHREADS) {
        int ci  = t % 48;
        int row = t / 48;
        int tri = ci / 3, p = ci % 3;
        int base = tri * 12 + p * (p + 1);   // 0, 2, 6
        int dep  = 2 * (p + 1);              // 2, 4, 6
        const float* rp = Ls + row * LPITCH + base;
        float s = 0.f;
        for (int qq = 0; qq < dep; qq++) s += rp[qq];
        g_conj[(size_t)(by * BM + row) * CDIM + bx * 48 + ci] =
            fast_tanh(s - (float)dep + 1.5f);
    }
}

// ---------------------------------------------------------------- finalize
#define RB 4

__global__ __launch_bounds__(256)
void finalize_kernel(const float* __restrict__ sigma, float* __restrict__ out)
{
    __shared__ float sc[RB][CDIM];
    __shared__ float red[8];
    __shared__ float xns[RB];

    const int tid = threadIdx.x;
    const int f   = tid;
    const int r0  = blockIdx.x * RB;
    const int lane = tid & 31, warp = tid >> 5;

#pragma unroll
    for (int r = 0; r < RB; r++) {
        const float4* src = (const float4*)(g_conj + (size_t)(r0 + r) * CDIM);
        float4* dst = (float4*)sc[r];
        for (int i = tid; i < CDIM / 4; i += 256) dst[i] = src[i];
    }
    if (tid < RB) xns[tid] = g_xn[r0 + tid];

    float dt[RB];
#pragma unroll
    for (int r = 0; r < RB; r++) dt[r] = g_dot[(size_t)(r0 + r) * DPITCH + f];

    const float mn    = g_mn[f];
    const float sig   = sigma[f];
    const float inv2s = 0.5f / (sig * sig);
    const int   g     = f >> 6;
    const int   nconj = 6 + 3 * g;
    const int   cstart = 96 * g * (g + 3) + (f & 63) * nconj;
    __syncthreads();

#pragma unroll
    for (int r = 0; r < RB; r++) {
        float s = 0.f;
        for (int q = 0; q < nconj; q++) s += sc[r][cstart + q];
        float dnnf = fast_tanh(s + (float)nconj - 1.5f);

        float sq = xns[r] - 2.f * dt[r] + mn;
        float logit = 2.0f * expf(-sq * inv2s);
        float e = expf(logit);

        float v = e;
#pragma unroll
        for (int off = 16; off > 0; off >>= 1)
            v += __shfl_xor_sync(0xffffffffu, v, off);
        if (lane == 0) red[warp] = v;
        __syncthreads();
        float tot = red[0] + red[1] + red[2] + red[3] +
                    red[4] + red[5] + red[6] + red[7];
        out[(size_t)(r0 + r) * FDIM + f] = dnnf * (e / tot);
        __syncthreads();
    }
}

// ---------------------------------------------------------------- launch
extern "C" void kernel_launch(void* const* d_in, const int* in_sizes, int n_in,
                              void* d_out, int out_size)
{
    const float* x     = (const float*)d_in[0];
    const float* w     = (const float*)d_in[1];
    const float* msk   = (const float*)d_in[2];
    const float* bias  = (const float*)d_in[3];
    const float* mu    = (const float*)d_in[4];
    const float* sigma = (const float*)d_in[5];
    float* out = (float*)d_out;

    cudaFuncSetAttribute(fused_gemm_dnf_kernel,
                         cudaFuncAttributeMaxDynamicSharedMemorySize, SMEM_NEED);

    prep_x_kernel<<<(BATCH * KDIM / 8 + 255) / 256, 256>>>(x);
    {
        dim3 g(LDIM / 32, KDIM / 32);
        dim3 b(32, 32);
        prep_w_kernel<<<g, b>>>(w, msk);
    }
    prep_mu_kernel<<<48, 256>>>(mu);
    xn_kernel<<<BATCH / 8, 256>>>(x);
    {
        dim3 grid(LDIM2 / BN, BATCH / BM);   // (58, 64)
        fused_gemm_dnf_kernel<<<grid, NTHREADS, SMEM_NEED>>>(bias);
    }
    finalize_kernel<<<BATCH / RB, 256>>>(sigma, out);
}

// round 8
// speedup vs baseline: 1.2102x; 1.2102x over previous
#include <cuda_runtime.h>
#include <cuda_fp16.h>
#include <cstdint>

// ----------------------------------------------------------------------------
// B = 8192, K = 512, L = 10752 literals, C = 2688 conj, F = 256
// fp16 mma.sync m16n8k16 GEMM; x@muT folded in as extra N-tiles.
// 128x192 CTA, 512 threads, warp tile 32x48, k16-level fragment double-buffer.
// ----------------------------------------------------------------------------
#define BATCH   8192
#define KDIM    512
#define LDIM    10752
#define LDIM2   11136        // + 256 mu rows + 128 zero pad
#define CDIM    2688
#define FDIM    256
#define DPITCH  384

#define BM 128
#define BN 192
#define BK 64
#define NTHREADS 512         // 16 warps: 4 (m) x 4 (n), warp tile 32 x 48
#define STAGE   40960
#define BOFF    16384
#define SM_BIAS (3 * STAGE)
#define SMEM_NEED (SM_BIAS + 768)
#define LPITCH  200
#define NLT     (LDIM / BN)  // 56 literal tiles; bx 56,57 are mu tiles

// scratch
__device__ __half g_A[(size_t)BATCH * KDIM];
__device__ __half g_B[(size_t)LDIM2 * KDIM];
__device__ float g_conj[(size_t)BATCH * CDIM];
__device__ float g_dot[(size_t)BATCH * DPITCH];
__device__ float g_xn[BATCH];
__device__ float g_mn[FDIM];

// ---------------------------------------------------------------- helpers
__device__ __forceinline__ uint32_t smem_u32(const void* p) {
    uint32_t a;
    asm("{ .reg .u64 t; cvta.to.shared.u64 t, %1; cvt.u32.u64 %0, t; }" : "=r"(a) : "l"(p));
    return a;
}
__device__ __forceinline__ void cp16(uint32_t dst, const void* src) {
    asm volatile("cp.async.cg.shared.global [%0], [%1], 16;" :: "r"(dst), "l"(src) : "memory");
}
#define CP_COMMIT() asm volatile("cp.async.commit_group;" ::: "memory")
#define CP_WAIT(n)  asm volatile("cp.async.wait_group %0;" :: "n"(n) : "memory")

__device__ __forceinline__ void ldsm_x4(uint32_t addr, uint32_t r[4]) {
    asm volatile("ldmatrix.sync.aligned.m8n8.x4.shared.b16 {%0,%1,%2,%3}, [%4];"
        : "=r"(r[0]), "=r"(r[1]), "=r"(r[2]), "=r"(r[3]) : "r"(addr));
}
__device__ __forceinline__ void mma_f16(float c[4], const uint32_t a[4],
                                        uint32_t b0, uint32_t b1) {
    asm volatile("mma.sync.aligned.m16n8k16.row.col.f32.f16.f16.f32 "
        "{%0,%1,%2,%3}, {%4,%5,%6,%7}, {%8,%9}, {%0,%1,%2,%3};"
        : "+f"(c[0]), "+f"(c[1]), "+f"(c[2]), "+f"(c[3])
        : "r"(a[0]), "r"(a[1]), "r"(a[2]), "r"(a[3]), "r"(b0), "r"(b1));
}

__device__ __forceinline__ float fast_tanh(float x) {
    float ax = fabsf(x);
    float t;
    asm("ex2.approx.f32 %0, %1;" : "=f"(t) : "f"(ax * -2.885390082f));
    float r = __fdividef(1.f - t, 1.f + t);
    return copysignf(r, x);
}

// ---------------------------------------------------------------- prep kernels
__global__ void prep_x_kernel(const float* __restrict__ x) {
    int i = blockIdx.x * blockDim.x + threadIdx.x;
    if (i >= BATCH * KDIM / 8) return;
    float4 v0 = *(const float4*)(x + (size_t)i * 8);
    float4 v1 = *(const float4*)(x + (size_t)i * 8 + 4);
    __half2 h[4];
    h[0] = __floats2half2_rn(v0.x, v0.y);
    h[1] = __floats2half2_rn(v0.z, v0.w);
    h[2] = __floats2half2_rn(v1.x, v1.y);
    h[3] = __floats2half2_rn(v1.z, v1.w);
    *(uint4*)(g_A + (size_t)i * 8) = *(uint4*)h;
}

__global__ void prep_w_kernel(const float* __restrict__ w, const float* __restrict__ m) {
    __shared__ float s[32][33];
    int n0 = blockIdx.x * 32, k0 = blockIdx.y * 32;
    int tx = threadIdx.x, ty = threadIdx.y;
    size_t gi = (size_t)(k0 + ty) * LDIM + n0 + tx;
    s[ty][tx] = w[gi] * m[gi];
    __syncthreads();
    g_B[(size_t)(n0 + ty) * KDIM + k0 + tx] = __float2half_rn(s[tx][ty]);
}

__global__ void prep_mu_kernel(const float* __restrict__ mu) {
    const int tid = threadIdx.x, wid = tid >> 5, lane = tid & 31;
    if (blockIdx.x < 32) {
        int f = blockIdx.x * 8 + wid;
        const float* src = mu + (size_t)f * KDIM;
        __half* dst = g_B + (size_t)(LDIM + f) * KDIM;
        float sq = 0.f;
#pragma unroll
        for (int j = 0; j < 4; j++) {
            int idx = lane + j * 32;
            float4 v = *(const float4*)(src + idx * 4);
            sq = fmaf(v.x, v.x, sq); sq = fmaf(v.y, v.y, sq);
            sq = fmaf(v.z, v.z, sq); sq = fmaf(v.w, v.w, sq);
            __half2 h0 = __floats2half2_rn(v.x, v.y);
            __half2 h1 = __floats2half2_rn(v.z, v.w);
            uint2 pk = make_uint2(*(uint32_t*)&h0, *(uint32_t*)&h1);
            *(uint2*)(dst + idx * 4) = pk;
        }
#pragma unroll
        for (int off = 16; off > 0; off >>= 1)
            sq += __shfl_xor_sync(0xffffffffu, sq, off);
        if (lane == 0) g_mn[f] = sq;
    } else {
        int row = LDIM + FDIM + (blockIdx.x - 32) * 8 + wid;
        __half* dst = g_B + (size_t)row * KDIM;
#pragma unroll
        for (int j = 0; j < 4; j++) {
            int idx = lane + j * 32;
            *(uint2*)(dst + idx * 4) = make_uint2(0u, 0u);
        }
    }
}

__global__ void xn_kernel(const float* __restrict__ x) {
    const int tid = threadIdx.x, wid = tid >> 5, lane = tid & 31;
    int row = blockIdx.x * 8 + wid;
    const float* src = x + (size_t)row * KDIM;
    float sq = 0.f;
#pragma unroll
    for (int j = 0; j < 4; j++) {
        int idx = lane + j * 32;
        float4 v = *(const float4*)(src + idx * 4);
        sq = fmaf(v.x, v.x, sq); sq = fmaf(v.y, v.y, sq);
        sq = fmaf(v.z, v.z, sq); sq = fmaf(v.w, v.w, sq);
    }
#pragma unroll
    for (int off = 16; off > 0; off >>= 1)
        sq += __shfl_xor_sync(0xffffffffu, sq, off);
    if (lane == 0) g_xn[row] = sq;
}

// ---------------------------------------------------------------- fused GEMM
__global__ __launch_bounds__(NTHREADS, 1)
void fused_gemm_dnf_kernel(const float* __restrict__ bias) {
    extern __shared__ char smp[];
    const uint32_t sb = smem_u32(smp);

    const int tid = threadIdx.x;
    const int wid = tid >> 5, lane = tid & 31;
    const int bx = blockIdx.x;   // 0..55 literals, 56..57 mu
    const int by = blockIdx.y;
    const int warp_m = wid & 3;
    const int warp_n = wid >> 2;

    float* sbias = (float*)(smp + SM_BIAS);
    if (tid < BN && bx < NLT) sbias[tid] = bias[bx * BN + tid];

    const __half* Ag = g_A + (size_t)(by * BM) * KDIM;
    const __half* Bg = g_B + (size_t)(bx * BN) * KDIM;

    const int r16 = lane & 15, l4 = lane >> 4;
    int am128[2], a7[2];
#pragma unroll
    for (int t = 0; t < 2; t++) {
        int row = warp_m * 32 + t * 16 + r16;
        am128[t] = row * 128; a7[t] = row & 7;
    }
    int bn128[3], b7[3];
#pragma unroll
    for (int i = 0; i < 3; i++) {
        int n = warp_n * 48 + i * 16 + r16;
        bn128[i] = n * 128; b7[i] = n & 7;
    }

    float c[2][6][4];
#pragma unroll
    for (int t = 0; t < 2; t++)
#pragma unroll
        for (int n = 0; n < 6; n++)
#pragma unroll
            for (int e = 0; e < 4; e++) c[t][n][e] = 0.f;

#define ISSUE(kt)                                                              \
    {                                                                          \
        const uint32_t stA = sb + ((kt) % 3) * STAGE;                          \
        _Pragma("unroll")                                                      \
        for (int j = 0; j < 2; j++) {                                          \
            int idx = tid + NTHREADS * j;                                      \
            int row = idx >> 3, ch = idx & 7;                                  \
            cp16(stA + row * 128 + ((ch ^ (row & 7)) << 4),                    \
                 Ag + (size_t)row * KDIM + (kt) * BK + ch * 8);                \
        }                                                                      \
        _Pragma("unroll")                                                      \
        for (int j = 0; j < 3; j++) {                                          \
            int idx = tid + NTHREADS * j;                                      \
            int row = idx >> 3, ch = idx & 7;                                  \
            cp16(stA + BOFF + row * 128 + ((ch ^ (row & 7)) << 4),             \
                 Bg + (size_t)row * KDIM + (kt) * BK + ch * 8);                \
        }                                                                      \
        CP_COMMIT();                                                           \
    }

    ISSUE(0);
    ISSUE(1);

    const int NKT = KDIM / BK;   // 8
    for (int kt = 0; kt < NKT; kt++) {
        CP_WAIT(1);
        __syncthreads();
        if (kt + 2 < NKT) { ISSUE(kt + 2); } else { CP_COMMIT(); }

        const uint32_t sA = sb + (kt % 3) * STAGE;
        const uint32_t sB = sA + BOFF;

        // double-buffered fragments at the k16 level
        uint32_t af[2][2][4], bf[2][3][4];
        {
            const int ch = l4;
#pragma unroll
            for (int t = 0; t < 2; t++)
                ldsm_x4(sA + am128[t] + ((ch ^ a7[t]) << 4), af[0][t]);
#pragma unroll
            for (int i = 0; i < 3; i++)
                ldsm_x4(sB + bn128[i] + ((ch ^ b7[i]) << 4), bf[0][i]);
        }
#pragma unroll
        for (int ks = 0; ks < 4; ks++) {
            const int cur = ks & 1, nxt = cur ^ 1;
            if (ks < 3) {
                const int ch = 2 * (ks + 1) + l4;
#pragma unroll
                for (int t = 0; t < 2; t++)
                    ldsm_x4(sA + am128[t] + ((ch ^ a7[t]) << 4), af[nxt][t]);
#pragma unroll
                for (int i = 0; i < 3; i++)
                    ldsm_x4(sB + bn128[i] + ((ch ^ b7[i]) << 4), bf[nxt][i]);
            }
#pragma unroll
            for (int t = 0; t < 2; t++)
#pragma unroll
                for (int i = 0; i < 3; i++) {
                    mma_f16(c[t][2 * i + 0], af[cur][t], bf[cur][i][0], bf[cur][i][2]);
                    mma_f16(c[t][2 * i + 1], af[cur][t], bf[cur][i][1], bf[cur][i][3]);
                }
        }
    }
#undef ISSUE

    CP_WAIT(0);
    __syncthreads();

    const int g = lane >> 2, cc = lane & 3;

    if (bx >= NLT) {
        // ------------- mu tiles: write raw dots to g_dot -------------
        const int colbase = bx * BN - LDIM;   // 0 or 192
        float* dp = g_dot + (size_t)(by * BM) * DPITCH + colbase;
#pragma unroll
        for (int t = 0; t < 2; t++) {
            int row0 = warp_m * 32 + t * 16 + g;
#pragma unroll
            for (int i = 0; i < 3; i++)
#pragma unroll
                for (int j = 0; j < 2; j++) {
                    int colb = warp_n * 48 + i * 16 + j * 8 + 2 * cc;
                    int nt = 2 * i + j;
                    *(float2*)(dp + (size_t)row0 * DPITCH + colb) =
                        make_float2(c[t][nt][0], c[t][nt][1]);
                    *(float2*)(dp + (size_t)(row0 + 8) * DPITCH + colb) =
                        make_float2(c[t][nt][2], c[t][nt][3]);
                }
        }
        return;
    }

    // ---------------- literal epilogue: tanh + conj reduce ----------------
    float* Ls = (float*)smp;   // [128][LPITCH]
#pragma unroll
    for (int t = 0; t < 2; t++) {
        int row0 = warp_m * 32 + t * 16 + g;
#pragma unroll
        for (int i = 0; i < 3; i++)
#pragma unroll
            for (int j = 0; j < 2; j++) {
                int colb = warp_n * 48 + i * 16 + j * 8 + 2 * cc;
                int nt = 2 * i + j;
                float b0 = sbias[colb], b1 = sbias[colb + 1];
                float2 v0, v1;
                v0.x = fast_tanh(c[t][nt][0] + b0);
                v0.y = fast_tanh(c[t][nt][1] + b1);
                v1.x = fast_tanh(c[t][nt][2] + b0);
                v1.y = fast_tanh(c[t][nt][3] + b1);
                *(float2*)(Ls + row0 * LPITCH + colb) = v0;
                *(float2*)(Ls + (row0 + 8) * LPITCH + colb) = v1;
            }
    }
    __syncthreads();

    for (int t = tid; t < BM * 48; t += NTHREADS) {
        int ci  = t % 48;
        int row = t / 48;
        int tri = ci / 3, p = ci % 3;
        int base = tri * 12 + p * (p + 1);
        int dep  = 2 * (p + 1);
        const float* rp = Ls + row * LPITCH + base;
        float s = 0.f;
        for (int qq = 0; qq < dep; qq++) s += rp[qq];
        g_conj[(size_t)(by * BM + row) * CDIM + bx * 48 + ci] =
            fast_tanh(s - (float)dep + 1.5f);
    }
}

// ---------------------------------------------------------------- finalize
#define RB 4

__global__ __launch_bounds__(256)
void finalize_kernel(const float* __restrict__ sigma, float* __restrict__ out)
{
    __shared__ float sc[RB][CDIM];
    __shared__ float red[8];
    __shared__ float xns[RB];

    const int tid = threadIdx.x;
    const int f   = tid;
    const int r0  = blockIdx.x * RB;
    const int lane = tid & 31, warp = tid >> 5;

#pragma unroll
    for (int r = 0; r < RB; r++) {
        const float4* src = (const float4*)(g_conj + (size_t)(r0 + r) * CDIM);
        float4* dst = (float4*)sc[r];
        for (int i = tid; i < CDIM / 4; i += 256) dst[i] = src[i];
    }
    if (tid < RB) xns[tid] = g_xn[r0 + tid];

    float dt[RB];
#pragma unroll
    for (int r = 0; r < RB; r++) dt[r] = g_dot[(size_t)(r0 + r) * DPITCH + f];

    const float mn    = g_mn[f];
    const float sig   = sigma[f];
    const float inv2s = 0.5f / (sig * sig);
    const int   g     = f >> 6;
    const int   nconj = 6 + 3 * g;
    const int   cstart = 96 * g * (g + 3) + (f & 63) * nconj;
    __syncthreads();

#pragma unroll
    for (int r = 0; r < RB; r++) {
        float s = 0.f;
        for (int q = 0; q < nconj; q++) s += sc[r][cstart + q];
        float dnnf = fast_tanh(s + (float)nconj - 1.5f);

        float sq = xns[r] - 2.f * dt[r] + mn;
        float logit = 2.0f * expf(-sq * inv2s);
        float e = expf(logit);

        float v = e;
#pragma unroll
        for (int off = 16; off > 0; off >>= 1)
            v += __shfl_xor_sync(0xffffffffu, v, off);
        if (lane == 0) red[warp] = v;
        __syncthreads();
        float tot = red[0] + red[1] + red[2] + red[3] +
                    red[4] + red[5] + red[6] + red[7];
        out[(size_t)(r0 + r) * FDIM + f] = dnnf * (e / tot);
        __syncthreads();
    }
}

// ---------------------------------------------------------------- launch
extern "C" void kernel_launch(void* const* d_in, const int* in_sizes, int n_in,
                              void* d_out, int out_size)
{
    const float* x     = (const float*)d_in[0];
    const float* w     = (const float*)d_in[1];
    const float* msk   = (const float*)d_in[2];
    const float* bias  = (const float*)d_in[3];
    const float* mu    = (const float*)d_in[4];
    const float* sigma = (const float*)d_in[5];
    float* out = (float*)d_out;

    cudaFuncSetAttribute(fused_gemm_dnf_kernel,
                         cudaFuncAttributeMaxDynamicSharedMemorySize, SMEM_NEED);

    prep_x_kernel<<<(BATCH * KDIM / 8 + 255) / 256, 256>>>(x);
    {
        dim3 g(LDIM / 32, KDIM / 32);
        dim3 b(32, 32);
        prep_w_kernel<<<g, b>>>(w, msk);
    }
    prep_mu_kernel<<<48, 256>>>(mu);
    xn_kernel<<<BATCH / 8, 256>>>(x);
    {
        dim3 grid(LDIM2 / BN, BATCH / BM);   // (58, 64)
        fused_gemm_dnf_kernel<<<grid, NTHREADS, SMEM_NEED>>>(bias);
    }
    finalize_kernel<<<BATCH / RB, 256>>>(sigma, out);
}

// round 9
// speedup vs baseline: 1.3525x; 1.1175x over previous
#include <cuda_runtime.h>
#include <cuda_fp16.h>
#include <cstdint>

// ----------------------------------------------------------------------------
// B = 8192, K = 512, L = 10752 literals, C = 2688 conj, F = 256
// fp16 mma.sync m16n8k16 GEMM; x@muT folded in as extra N-tiles.
// 128x96 CTA, 256 threads, 2 CTAs/SM; fully unrolled mainloop.
// ----------------------------------------------------------------------------
#define BATCH   8192
#define KDIM    512
#define LDIM    10752
#define LDIM2   11136        // + 256 mu rows + 128 zero pad
#define CDIM    2688
#define FDIM    256
#define DPITCH  384

#define BM 128
#define BN 96                // 8 triples = 24 conjunctions (triple-aligned)
#define BK 64
#define NTHREADS 256         // 8 warps: 4 (m) x 2 (n), warp tile 32 x 48
#define STAGE   28672        // (128+96)*128 bytes
#define BOFF    16384
#define SM_BIAS (3 * STAGE)  // 86016
#define SMEM_NEED (SM_BIAS + 384)
#define LPITCH  104
#define NLT     (LDIM / BN)  // 112 literal tiles; bx 112..115 are mu tiles

// scratch
__device__ __half g_A[(size_t)BATCH * KDIM];
__device__ __half g_B[(size_t)LDIM2 * KDIM];
__device__ float g_conj[(size_t)BATCH * CDIM];
__device__ float g_dot[(size_t)BATCH * DPITCH];
__device__ float g_xn[BATCH];
__device__ float g_mn[FDIM];

// ---------------------------------------------------------------- helpers
__device__ __forceinline__ uint32_t smem_u32(const void* p) {
    uint32_t a;
    asm("{ .reg .u64 t; cvta.to.shared.u64 t, %1; cvt.u32.u64 %0, t; }" : "=r"(a) : "l"(p));
    return a;
}
__device__ __forceinline__ void cp16(uint32_t dst, const void* src) {
    asm volatile("cp.async.cg.shared.global [%0], [%1], 16;" :: "r"(dst), "l"(src) : "memory");
}
#define CP_COMMIT() asm volatile("cp.async.commit_group;" ::: "memory")
#define CP_WAIT(n)  asm volatile("cp.async.wait_group %0;" :: "n"(n) : "memory")

__device__ __forceinline__ void ldsm_x4(uint32_t addr, uint32_t r[4]) {
    asm volatile("ldmatrix.sync.aligned.m8n8.x4.shared.b16 {%0,%1,%2,%3}, [%4];"
        : "=r"(r[0]), "=r"(r[1]), "=r"(r[2]), "=r"(r[3]) : "r"(addr));
}
__device__ __forceinline__ void mma_f16(float c[4], const uint32_t a[4],
                                        uint32_t b0, uint32_t b1) {
    asm volatile("mma.sync.aligned.m16n8k16.row.col.f32.f16.f16.f32 "
        "{%0,%1,%2,%3}, {%4,%5,%6,%7}, {%8,%9}, {%0,%1,%2,%3};"
        : "+f"(c[0]), "+f"(c[1]), "+f"(c[2]), "+f"(c[3])
        : "r"(a[0]), "r"(a[1]), "r"(a[2]), "r"(a[3]), "r"(b0), "r"(b1));
}

__device__ __forceinline__ float fast_tanh(float x) {
    float ax = fabsf(x);
    float t;
    asm("ex2.approx.f32 %0, %1;" : "=f"(t) : "f"(ax * -2.885390082f));
    float r = __fdividef(1.f - t, 1.f + t);
    return copysignf(r, x);
}

// ---------------------------------------------------------------- prep kernels
// fused: x -> fp16 g_A  AND  g_xn = ||x_row||^2   (warp per row)
__global__ void prep_x_xn_kernel(const float* __restrict__ x) {
    const int tid = threadIdx.x, wid = tid >> 5, lane = tid & 31;
    int row = blockIdx.x * 8 + wid;
    const float* src = x + (size_t)row * KDIM;
    __half* dst = g_A + (size_t)row * KDIM;
    float sq = 0.f;
#pragma unroll
    for (int j = 0; j < 4; j++) {
        int idx = lane + j * 32;
        float4 v = *(const float4*)(src + idx * 4);
        sq = fmaf(v.x, v.x, sq); sq = fmaf(v.y, v.y, sq);
        sq = fmaf(v.z, v.z, sq); sq = fmaf(v.w, v.w, sq);
        __half2 h0 = __floats2half2_rn(v.x, v.y);
        __half2 h1 = __floats2half2_rn(v.z, v.w);
        *(uint2*)(dst + idx * 4) = make_uint2(*(uint32_t*)&h0, *(uint32_t*)&h1);
    }
#pragma unroll
    for (int off = 16; off > 0; off >>= 1)
        sq += __shfl_xor_sync(0xffffffffu, sq, off);
    if (lane == 0) g_xn[row] = sq;
}

__global__ void prep_w_kernel(const float* __restrict__ w, const float* __restrict__ m) {
    __shared__ float s[32][33];
    int n0 = blockIdx.x * 32, k0 = blockIdx.y * 32;
    int tx = threadIdx.x, ty = threadIdx.y;
    size_t gi = (size_t)(k0 + ty) * LDIM + n0 + tx;
    s[ty][tx] = w[gi] * m[gi];
    __syncthreads();
    g_B[(size_t)(n0 + ty) * KDIM + k0 + tx] = __float2half_rn(s[tx][ty]);
}

__global__ void prep_mu_kernel(const float* __restrict__ mu) {
    const int tid = threadIdx.x, wid = tid >> 5, lane = tid & 31;
    if (blockIdx.x < 32) {
        int f = blockIdx.x * 8 + wid;
        const float* src = mu + (size_t)f * KDIM;
        __half* dst = g_B + (size_t)(LDIM + f) * KDIM;
        float sq = 0.f;
#pragma unroll
        for (int j = 0; j < 4; j++) {
            int idx = lane + j * 32;
            float4 v = *(const float4*)(src + idx * 4);
            sq = fmaf(v.x, v.x, sq); sq = fmaf(v.y, v.y, sq);
            sq = fmaf(v.z, v.z, sq); sq = fmaf(v.w, v.w, sq);
            __half2 h0 = __floats2half2_rn(v.x, v.y);
            __half2 h1 = __floats2half2_rn(v.z, v.w);
            *(uint2*)(dst + idx * 4) = make_uint2(*(uint32_t*)&h0, *(uint32_t*)&h1);
        }
#pragma unroll
        for (int off = 16; off > 0; off >>= 1)
            sq += __shfl_xor_sync(0xffffffffu, sq, off);
        if (lane == 0) g_mn[f] = sq;
    } else {
        int row = LDIM + FDIM + (blockIdx.x - 32) * 8 + wid;
        __half* dst = g_B + (size_t)row * KDIM;
#pragma unroll
        for (int j = 0; j < 4; j++) {
            int idx = lane + j * 32;
            *(uint2*)(dst + idx * 4) = make_uint2(0u, 0u);
        }
    }
}

// ---------------------------------------------------------------- fused GEMM
__global__ __launch_bounds__(NTHREADS, 2)
void fused_gemm_dnf_kernel(const float* __restrict__ bias) {
    extern __shared__ char smp[];
    const uint32_t sb = smem_u32(smp);

    const int tid = threadIdx.x;
    const int wid = tid >> 5, lane = tid & 31;
    const int bx = blockIdx.x;   // 0..111 literals, 112..115 mu
    const int by = blockIdx.y;
    const int warp_m = wid & 3;
    const int warp_n = wid >> 2;

    float* sbias = (float*)(smp + SM_BIAS);
    if (tid < BN && bx < NLT) sbias[tid] = bias[bx * BN + tid];

    const __half* Ag = g_A + (size_t)(by * BM) * KDIM;
    const __half* Bg = g_B + (size_t)(bx * BN) * KDIM;

    const int r16 = lane & 15, l4 = lane >> 4;
    int am128[2], a7[2];
#pragma unroll
    for (int t = 0; t < 2; t++) {
        int row = warp_m * 32 + t * 16 + r16;
        am128[t] = row * 128; a7[t] = row & 7;
    }
    int bn128[3], b7[3];
#pragma unroll
    for (int i = 0; i < 3; i++) {
        int n = warp_n * 48 + i * 16 + r16;
        bn128[i] = n * 128; b7[i] = n & 7;
    }

    float c[2][6][4];
#pragma unroll
    for (int t = 0; t < 2; t++)
#pragma unroll
        for (int n = 0; n < 6; n++)
#pragma unroll
            for (int e = 0; e < 4; e++) c[t][n][e] = 0.f;

    // A: 128 rows x 8 chunks = 1024 ops (4/thread), B: 96 x 8 = 768 (3/thread)
#define ISSUE(kt)                                                              \
    {                                                                          \
        const uint32_t stA = sb + ((kt) % 3) * STAGE;                          \
        _Pragma("unroll")                                                      \
        for (int j = 0; j < 4; j++) {                                          \
            int idx = tid + NTHREADS * j;                                      \
            int row = idx >> 3, ch = idx & 7;                                  \
            cp16(stA + row * 128 + ((ch ^ (row & 7)) << 4),                    \
                 Ag + (size_t)row * KDIM + (kt) * BK + ch * 8);                \
        }                                                                      \
        _Pragma("unroll")                                                      \
        for (int j = 0; j < 3; j++) {                                          \
            int idx = tid + NTHREADS * j;                                      \
            int row = idx >> 3, ch = idx & 7;                                  \
            cp16(stA + BOFF + row * 128 + ((ch ^ (row & 7)) << 4),             \
                 Bg + (size_t)row * KDIM + (kt) * BK + ch * 8);                \
        }                                                                      \
        CP_COMMIT();                                                           \
    }

    ISSUE(0);
    ISSUE(1);

    const int NKT = KDIM / BK;   // 8
#pragma unroll
    for (int kt = 0; kt < NKT; kt++) {
        CP_WAIT(1);
        __syncthreads();
        if (kt + 2 < NKT) { ISSUE(kt + 2); } else { CP_COMMIT(); }

        const uint32_t sA = sb + (kt % 3) * STAGE;
        const uint32_t sB = sA + BOFF;
#pragma unroll
        for (int ks = 0; ks < 4; ks++) {
            uint32_t af[2][4], bf[3][4];
            const int ch = 2 * ks + l4;
#pragma unroll
            for (int t = 0; t < 2; t++)
                ldsm_x4(sA + am128[t] + ((ch ^ a7[t]) << 4), af[t]);
#pragma unroll
            for (int i = 0; i < 3; i++)
                ldsm_x4(sB + bn128[i] + ((ch ^ b7[i]) << 4), bf[i]);
#pragma unroll
            for (int t = 0; t < 2; t++)
#pragma unroll
                for (int i = 0; i < 3; i++) {
                    mma_f16(c[t][2 * i + 0], af[t], bf[i][0], bf[i][2]);
                    mma_f16(c[t][2 * i + 1], af[t], bf[i][1], bf[i][3]);
                }
        }
    }
#undef ISSUE

    CP_WAIT(0);
    __syncthreads();

    const int g = lane >> 2, cc = lane & 3;

    if (bx >= NLT) {
        // ------------- mu tiles: write raw dots to g_dot -------------
        const int colbase = bx * BN - LDIM;   // 0, 96, 192, 288
        float* dp = g_dot + (size_t)(by * BM) * DPITCH + colbase;
#pragma unroll
        for (int t = 0; t < 2; t++) {
            int row0 = warp_m * 32 + t * 16 + g;
#pragma unroll
            for (int i = 0; i < 3; i++)
#pragma unroll
                for (int j = 0; j < 2; j++) {
                    int colb = warp_n * 48 + i * 16 + j * 8 + 2 * cc;
                    int nt = 2 * i + j;
                    *(float2*)(dp + (size_t)row0 * DPITCH + colb) =
                        make_float2(c[t][nt][0], c[t][nt][1]);
                    *(float2*)(dp + (size_t)(row0 + 8) * DPITCH + colb) =
                        make_float2(c[t][nt][2], c[t][nt][3]);
                }
        }
        return;
    }

    // ---------------- literal epilogue: tanh + conj reduce ----------------
    float* Ls = (float*)smp;   // [128][LPITCH]
#pragma unroll
    for (int t = 0; t < 2; t++) {
        int row0 = warp_m * 32 + t * 16 + g;
#pragma unroll
        for (int i = 0; i < 3; i++)
#pragma unroll
            for (int j = 0; j < 2; j++) {
                int colb = warp_n * 48 + i * 16 + j * 8 + 2 * cc;
                int nt = 2 * i + j;
                float b0 = sbias[colb], b1 = sbias[colb + 1];
                float2 v0, v1;
                v0.x = fast_tanh(c[t][nt][0] + b0);
                v0.y = fast_tanh(c[t][nt][1] + b1);
                v1.x = fast_tanh(c[t][nt][2] + b0);
                v1.y = fast_tanh(c[t][nt][3] + b1);
                *(float2*)(Ls + row0 * LPITCH + colb) = v0;
                *(float2*)(Ls + (row0 + 8) * LPITCH + colb) = v1;
            }
    }
    __syncthreads();

    // 128 rows x 24 conj = 3072 tasks
    for (int t = tid; t < BM * 24; t += NTHREADS) {
        int ci  = t % 24;
        int row = t / 24;
        int tri = ci / 3, p = ci % 3;
        int base = tri * 12 + p * (p + 1);   // 0, 2, 6
        int dep  = 2 * (p + 1);              // 2, 4, 6
        const float* rp = Ls + row * LPITCH + base;
        float s = 0.f;
        for (int qq = 0; qq < dep; qq++) s += rp[qq];
        g_conj[(size_t)(by * BM + row) * CDIM + bx * 24 + ci] =
            fast_tanh(s - (float)dep + 1.5f);
    }
}

// ---------------------------------------------------------------- finalize
#define RB 4

__global__ __launch_bounds__(256)
void finalize_kernel(const float* __restrict__ sigma, float* __restrict__ out)
{
    __shared__ float sc[RB][CDIM];
    __shared__ float red[8];
    __shared__ float xns[RB];

    const int tid = threadIdx.x;
    const int f   = tid;
    const int r0  = blockIdx.x * RB;
    const int lane = tid & 31, warp = tid >> 5;

#pragma unroll
    for (int r = 0; r < RB; r++) {
        const float4* src = (const float4*)(g_conj + (size_t)(r0 + r) * CDIM);
        float4* dst = (float4*)sc[r];
        for (int i = tid; i < CDIM / 4; i += 256) dst[i] = src[i];
    }
    if (tid < RB) xns[tid] = g_xn[r0 + tid];

    float dt[RB];
#pragma unroll
    for (int r = 0; r < RB; r++) dt[r] = g_dot[(size_t)(r0 + r) * DPITCH + f];

    const float mn    = g_mn[f];
    const float sig   = sigma[f];
    const float inv2s = 0.5f / (sig * sig);
    const int   g     = f >> 6;
    const int   nconj = 6 + 3 * g;
    const int   cstart = 96 * g * (g + 3) + (f & 63) * nconj;
    __syncthreads();

#pragma unroll
    for (int r = 0; r < RB; r++) {
        float s = 0.f;
        for (int q = 0; q < nconj; q++) s += sc[r][cstart + q];
        float dnnf = fast_tanh(s + (float)nconj - 1.5f);

        float sq = xns[r] - 2.f * dt[r] + mn;
        float logit = 2.0f * expf(-sq * inv2s);
        float e = expf(logit);

        float v = e;
#pragma unroll
        for (int off = 16; off > 0; off >>= 1)
            v += __shfl_xor_sync(0xffffffffu, v, off);
        if (lane == 0) red[warp] = v;
        __syncthreads();
        float tot = red[0] + red[1] + red[2] + red[3] +
                    red[4] + red[5] + red[6] + red[7];
        out[(size_t)(r0 + r) * FDIM + f] = dnnf * (e / tot);
        __syncthreads();
    }
}

// ---------------------------------------------------------------- launch
extern "C" void kernel_launch(void* const* d_in, const int* in_sizes, int n_in,
                              void* d_out, int out_size)
{
    const float* x     = (const float*)d_in[0];
    const float* w     = (const float*)d_in[1];
    const float* msk   = (const float*)d_in[2];
    const float* bias  = (const float*)d_in[3];
    const float* mu    = (const float*)d_in[4];
    const float* sigma = (const float*)d_in[5];
    float* out = (float*)d_out;

    cudaFuncSetAttribute(fused_gemm_dnf_kernel,
                         cudaFuncAttributeMaxDynamicSharedMemorySize, SMEM_NEED);

    prep_x_xn_kernel<<<BATCH / 8, 256>>>(x);
    {
        dim3 g(LDIM / 32, KDIM / 32);
        dim3 b(32, 32);
        prep_w_kernel<<<g, b>>>(w, msk);
    }
    prep_mu_kernel<<<48, 256>>>(mu);
    {
        dim3 grid(LDIM2 / BN, BATCH / BM);   // (116, 64)
        fused_gemm_dnf_kernel<<<grid, NTHREADS, SMEM_NEED>>>(bias);
    }
    finalize_kernel<<<BATCH / RB, 256>>>(sigma, out);
}

// round 10
// speedup vs baseline: 1.3901x; 1.0278x over previous
#include <cuda_runtime.h>
#include <cuda_fp16.h>
#include <cstdint>

// ----------------------------------------------------------------------------
// B = 8192, K = 512, L = 10752 literals, C = 2688 conj, F = 256
// fp16 mma.sync m16n8k16 GEMM; x@muT folded in as extra N-tiles.
// 128x96 CTA, 256 threads, 2 CTAs/SM; fp16 conj scratch.
// ----------------------------------------------------------------------------
#define BATCH   8192
#define KDIM    512
#define LDIM    10752
#define LDIM2   11040        // + 256 mu rows + 32 zero pad (115 tiles exactly)
#define CDIM    2688
#define FDIM    256
#define DPITCH  384

#define BM 128
#define BN 96                // 8 triples = 24 conjunctions (triple-aligned)
#define BK 64
#define NTHREADS 256         // 8 warps: 4 (m) x 2 (n), warp tile 32 x 48
#define STAGE   28672        // (128+96)*128 bytes
#define BOFF    16384
#define SM_BIAS (3 * STAGE)  // 86016
#define SMEM_NEED (SM_BIAS + 384)
#define LPITCH  104
#define NLT     (LDIM / BN)  // 112 literal tiles; bx 112..114 are mu tiles

// scratch
__device__ __half g_A[(size_t)BATCH * KDIM];
__device__ __half g_B[(size_t)LDIM2 * KDIM];
__device__ __half g_conj[(size_t)BATCH * CDIM];
__device__ float g_dot[(size_t)BATCH * DPITCH];
__device__ float g_xn[BATCH];
__device__ float g_mn[FDIM];

// ---------------------------------------------------------------- helpers
__device__ __forceinline__ uint32_t smem_u32(const void* p) {
    uint32_t a;
    asm("{ .reg .u64 t; cvta.to.shared.u64 t, %1; cvt.u32.u64 %0, t; }" : "=r"(a) : "l"(p));
    return a;
}
__device__ __forceinline__ void cp16(uint32_t dst, const void* src) {
    asm volatile("cp.async.cg.shared.global [%0], [%1], 16;" :: "r"(dst), "l"(src) : "memory");
}
#define CP_COMMIT() asm volatile("cp.async.commit_group;" ::: "memory")
#define CP_WAIT(n)  asm volatile("cp.async.wait_group %0;" :: "n"(n) : "memory")

__device__ __forceinline__ void ldsm_x4(uint32_t addr, uint32_t r[4]) {
    asm volatile("ldmatrix.sync.aligned.m8n8.x4.shared.b16 {%0,%1,%2,%3}, [%4];"
        : "=r"(r[0]), "=r"(r[1]), "=r"(r[2]), "=r"(r[3]) : "r"(addr));
}
__device__ __forceinline__ void mma_f16(float c[4], const uint32_t a[4],
                                        uint32_t b0, uint32_t b1) {
    asm volatile("mma.sync.aligned.m16n8k16.row.col.f32.f16.f16.f32 "
        "{%0,%1,%2,%3}, {%4,%5,%6,%7}, {%8,%9}, {%0,%1,%2,%3};"
        : "+f"(c[0]), "+f"(c[1]), "+f"(c[2]), "+f"(c[3])
        : "r"(a[0]), "r"(a[1]), "r"(a[2]), "r"(a[3]), "r"(b0), "r"(b1));
}

__device__ __forceinline__ float fast_tanh(float x) {
    float ax = fabsf(x);
    float t;
    asm("ex2.approx.f32 %0, %1;" : "=f"(t) : "f"(ax * -2.885390082f));
    float r = __fdividef(1.f - t, 1.f + t);
    return copysignf(r, x);
}

// ---------------------------------------------------------------- prep kernels
// fused: x -> fp16 g_A  AND  g_xn = ||x_row||^2   (warp per row)
__global__ void prep_x_xn_kernel(const float* __restrict__ x) {
    const int tid = threadIdx.x, wid = tid >> 5, lane = tid & 31;
    int row = blockIdx.x * 8 + wid;
    const float* src = x + (size_t)row * KDIM;
    __half* dst = g_A + (size_t)row * KDIM;
    float sq = 0.f;
#pragma unroll
    for (int j = 0; j < 4; j++) {
        int idx = lane + j * 32;
        float4 v = *(const float4*)(src + idx * 4);
        sq = fmaf(v.x, v.x, sq); sq = fmaf(v.y, v.y, sq);
        sq = fmaf(v.z, v.z, sq); sq = fmaf(v.w, v.w, sq);
        __half2 h0 = __floats2half2_rn(v.x, v.y);
        __half2 h1 = __floats2half2_rn(v.z, v.w);
        *(uint2*)(dst + idx * 4) = make_uint2(*(uint32_t*)&h0, *(uint32_t*)&h1);
    }
#pragma unroll
    for (int off = 16; off > 0; off >>= 1)
        sq += __shfl_xor_sync(0xffffffffu, sq, off);
    if (lane == 0) g_xn[row] = sq;
}

__global__ void prep_w_kernel(const float* __restrict__ w, const float* __restrict__ m) {
    __shared__ float s[32][33];
    int n0 = blockIdx.x * 32, k0 = blockIdx.y * 32;
    int tx = threadIdx.x, ty = threadIdx.y;
    size_t gi = (size_t)(k0 + ty) * LDIM + n0 + tx;
    s[ty][tx] = w[gi] * m[gi];
    __syncthreads();
    g_B[(size_t)(n0 + ty) * KDIM + k0 + tx] = __float2half_rn(s[tx][ty]);
}

__global__ void prep_mu_kernel(const float* __restrict__ mu) {
    const int tid = threadIdx.x, wid = tid >> 5, lane = tid & 31;
    if (blockIdx.x < 32) {
        int f = blockIdx.x * 8 + wid;
        const float* src = mu + (size_t)f * KDIM;
        __half* dst = g_B + (size_t)(LDIM + f) * KDIM;
        float sq = 0.f;
#pragma unroll
        for (int j = 0; j < 4; j++) {
            int idx = lane + j * 32;
            float4 v = *(const float4*)(src + idx * 4);
            sq = fmaf(v.x, v.x, sq); sq = fmaf(v.y, v.y, sq);
            sq = fmaf(v.z, v.z, sq); sq = fmaf(v.w, v.w, sq);
            __half2 h0 = __floats2half2_rn(v.x, v.y);
            __half2 h1 = __floats2half2_rn(v.z, v.w);
            *(uint2*)(dst + idx * 4) = make_uint2(*(uint32_t*)&h0, *(uint32_t*)&h1);
        }
#pragma unroll
        for (int off = 16; off > 0; off >>= 1)
            sq += __shfl_xor_sync(0xffffffffu, sq, off);
        if (lane == 0) g_mn[f] = sq;
    } else {
        // pad rows 11008..11039 (4 blocks x 8 warps)
        int row = LDIM + FDIM + (blockIdx.x - 32) * 8 + wid;
        __half* dst = g_B + (size_t)row * KDIM;
#pragma unroll
        for (int j = 0; j < 4; j++) {
            int idx = lane + j * 32;
            *(uint2*)(dst + idx * 4) = make_uint2(0u, 0u);
        }
    }
}

// ---------------------------------------------------------------- fused GEMM
__global__ __launch_bounds__(NTHREADS, 2)
void fused_gemm_dnf_kernel(const float* __restrict__ bias) {
    extern __shared__ char smp[];
    const uint32_t sb = smem_u32(smp);

    const int tid = threadIdx.x;
    const int wid = tid >> 5, lane = tid & 31;
    const int bx = blockIdx.x;   // 0..111 literals, 112..114 mu
    const int by = blockIdx.y;
    const int warp_m = wid & 3;
    const int warp_n = wid >> 2;

    float* sbias = (float*)(smp + SM_BIAS);
    if (tid < BN && bx < NLT) sbias[tid] = bias[bx * BN + tid];

    const __half* Ag = g_A + (size_t)(by * BM) * KDIM;
    const __half* Bg = g_B + (size_t)(bx * BN) * KDIM;

    const int r16 = lane & 15, l4 = lane >> 4;
    int am128[2], a7[2];
#pragma unroll
    for (int t = 0; t < 2; t++) {
        int row = warp_m * 32 + t * 16 + r16;
        am128[t] = row * 128; a7[t] = row & 7;
    }
    int bn128[3], b7[3];
#pragma unroll
    for (int i = 0; i < 3; i++) {
        int n = warp_n * 48 + i * 16 + r16;
        bn128[i] = n * 128; b7[i] = n & 7;
    }

    float c[2][6][4];
#pragma unroll
    for (int t = 0; t < 2; t++)
#pragma unroll
        for (int n = 0; n < 6; n++)
#pragma unroll
            for (int e = 0; e < 4; e++) c[t][n][e] = 0.f;

#define ISSUE(kt)                                                              \
    {                                                                          \
        const uint32_t stA = sb + ((kt) % 3) * STAGE;                          \
        _Pragma("unroll")                                                      \
        for (int j = 0; j < 4; j++) {                                          \
            int idx = tid + NTHREADS * j;                                      \
            int row = idx >> 3, ch = idx & 7;                                  \
            cp16(stA + row * 128 + ((ch ^ (row & 7)) << 4),                    \
                 Ag + (size_t)row * KDIM + (kt) * BK + ch * 8);                \
        }                                                                      \
        _Pragma("unroll")                                                      \
        for (int j = 0; j < 3; j++) {                                          \
            int idx = tid + NTHREADS * j;                                      \
            int row = idx >> 3, ch = idx & 7;                                  \
            cp16(stA + BOFF + row * 128 + ((ch ^ (row & 7)) << 4),             \
                 Bg + (size_t)row * KDIM + (kt) * BK + ch * 8);                \
        }                                                                      \
        CP_COMMIT();                                                           \
    }

    ISSUE(0);
    ISSUE(1);

    const int NKT = KDIM / BK;   // 8
#pragma unroll
    for (int kt = 0; kt < NKT; kt++) {
        CP_WAIT(1);
        __syncthreads();
        if (kt + 2 < NKT) { ISSUE(kt + 2); } else { CP_COMMIT(); }

        const uint32_t sA = sb + (kt % 3) * STAGE;
        const uint32_t sB = sA + BOFF;
#pragma unroll
        for (int ks = 0; ks < 4; ks++) {
            uint32_t af[2][4], bf[3][4];
            const int ch = 2 * ks + l4;
#pragma unroll
            for (int t = 0; t < 2; t++)
                ldsm_x4(sA + am128[t] + ((ch ^ a7[t]) << 4), af[t]);
#pragma unroll
            for (int i = 0; i < 3; i++)
                ldsm_x4(sB + bn128[i] + ((ch ^ b7[i]) << 4), bf[i]);
#pragma unroll
            for (int t = 0; t < 2; t++)
#pragma unroll
                for (int i = 0; i < 3; i++) {
                    mma_f16(c[t][2 * i + 0], af[t], bf[i][0], bf[i][2]);
                    mma_f16(c[t][2 * i + 1], af[t], bf[i][1], bf[i][3]);
                }
        }
    }
#undef ISSUE

    CP_WAIT(0);
    __syncthreads();

    const int g = lane >> 2, cc = lane & 3;

    if (bx >= NLT) {
        // ------------- mu tiles: write raw dots to g_dot -------------
        const int colbase = bx * BN - LDIM;   // 0, 96, 192
        float* dp = g_dot + (size_t)(by * BM) * DPITCH + colbase;
#pragma unroll
        for (int t = 0; t < 2; t++) {
            int row0 = warp_m * 32 + t * 16 + g;
#pragma unroll
            for (int i = 0; i < 3; i++)
#pragma unroll
                for (int j = 0; j < 2; j++) {
                    int colb = warp_n * 48 + i * 16 + j * 8 + 2 * cc;
                    int nt = 2 * i + j;
                    *(float2*)(dp + (size_t)row0 * DPITCH + colb) =
                        make_float2(c[t][nt][0], c[t][nt][1]);
                    *(float2*)(dp + (size_t)(row0 + 8) * DPITCH + colb) =
                        make_float2(c[t][nt][2], c[t][nt][3]);
                }
        }
        return;
    }

    // ---------------- literal epilogue: tanh + conj reduce ----------------
    float* Ls = (float*)smp;   // [128][LPITCH]
#pragma unroll
    for (int t = 0; t < 2; t++) {
        int row0 = warp_m * 32 + t * 16 + g;
#pragma unroll
        for (int i = 0; i < 3; i++)
#pragma unroll
            for (int j = 0; j < 2; j++) {
                int colb = warp_n * 48 + i * 16 + j * 8 + 2 * cc;
                int nt = 2 * i + j;
                float b0 = sbias[colb], b1 = sbias[colb + 1];
                float2 v0, v1;
                v0.x = fast_tanh(c[t][nt][0] + b0);
                v0.y = fast_tanh(c[t][nt][1] + b1);
                v1.x = fast_tanh(c[t][nt][2] + b0);
                v1.y = fast_tanh(c[t][nt][3] + b1);
                *(float2*)(Ls + row0 * LPITCH + colb) = v0;
                *(float2*)(Ls + (row0 + 8) * LPITCH + colb) = v1;
            }
    }
    __syncthreads();

    // 128 rows x 24 conj = 3072 tasks, fp16 output
    for (int t = tid; t < BM * 24; t += NTHREADS) {
        int ci  = t % 24;
        int row = t / 24;
        int tri = ci / 3, p = ci % 3;
        int base = tri * 12 + p * (p + 1);   // 0, 2, 6
        int dep  = 2 * (p + 1);              // 2, 4, 6
        const float* rp = Ls + row * LPITCH + base;
        float s = 0.f;
        for (int qq = 0; qq < dep; qq++) s += rp[qq];
        g_conj[(size_t)(by * BM + row) * CDIM + bx * 24 + ci] =
            __float2half_rn(fast_tanh(s - (float)dep + 1.5f));
    }
}

// ---------------------------------------------------------------- finalize
#define RB 8

__global__ __launch_bounds__(256)
void finalize_kernel(const float* __restrict__ sigma, float* __restrict__ out)
{
    __shared__ __half sc[RB][CDIM];   // 43 KB
    __shared__ float red[8];
    __shared__ float xns[RB];

    const int tid = threadIdx.x;
    const int f   = tid;
    const int r0  = blockIdx.x * RB;
    const int lane = tid & 31, warp = tid >> 5;

#pragma unroll
    for (int r = 0; r < RB; r++) {
        const uint4* src = (const uint4*)(g_conj + (size_t)(r0 + r) * CDIM);
        uint4* dst = (uint4*)sc[r];
        for (int i = tid; i < CDIM / 8; i += 256) dst[i] = src[i];
    }
    if (tid < RB) xns[tid] = g_xn[r0 + tid];

    float dt[RB];
#pragma unroll
    for (int r = 0; r < RB; r++) dt[r] = g_dot[(size_t)(r0 + r) * DPITCH + f];

    const float mn    = g_mn[f];
    const float sig   = sigma[f];
    const float inv2s = 0.5f / (sig * sig);
    const int   g     = f >> 6;
    const int   nconj = 6 + 3 * g;
    const int   cstart = 96 * g * (g + 3) + (f & 63) * nconj;
    __syncthreads();

#pragma unroll
    for (int r = 0; r < RB; r++) {
        float s = 0.f;
        for (int q = 0; q < nconj; q++) s += __half2float(sc[r][cstart + q]);
        float dnnf = fast_tanh(s + (float)nconj - 1.5f);

        float sq = xns[r] - 2.f * dt[r] + mn;
        float logit = 2.0f * expf(-sq * inv2s);
        float e = expf(logit);

        float v = e;
#pragma unroll
        for (int off = 16; off > 0; off >>= 1)
            v += __shfl_xor_sync(0xffffffffu, v, off);
        if (lane == 0) red[warp] = v;
        __syncthreads();
        float tot = red[0] + red[1] + red[2] + red[3] +
                    red[4] + red[5] + red[6] + red[7];
        out[(size_t)(r0 + r) * FDIM + f] = dnnf * (e / tot);
        __syncthreads();
    }
}

// ---------------------------------------------------------------- launch
extern "C" void kernel_launch(void* const* d_in, const int* in_sizes, int n_in,
                              void* d_out, int out_size)
{
    const float* x     = (const float*)d_in[0];
    const float* w     = (const float*)d_in[1];
    const float* msk   = (const float*)d_in[2];
    const float* bias  = (const float*)d_in[3];
    const float* mu    = (const float*)d_in[4];
    const float* sigma = (const float*)d_in[5];
    float* out = (float*)d_out;

    cudaFuncSetAttribute(fused_gemm_dnf_kernel,
                         cudaFuncAttributeMaxDynamicSharedMemorySize, SMEM_NEED);

    prep_x_xn_kernel<<<BATCH / 8, 256>>>(x);
    {
        dim3 g(LDIM / 32, KDIM / 32);
        dim3 b(32, 32);
        prep_w_kernel<<<g, b>>>(w, msk);
    }
    prep_mu_kernel<<<36, 256>>>(mu);
    {
        dim3 grid(LDIM2 / BN, BATCH / BM);   // (115, 64)
        fused_gemm_dnf_kernel<<<grid, NTHREADS, SMEM_NEED>>>(bias);
    }
    finalize_kernel<<<BATCH / RB, 256>>>(sigma, out);
}

// round 11
// speedup vs baseline: 1.4251x; 1.0252x over previous
#include <cuda_runtime.h>
#include <cuda_fp16.h>
#include <cstdint>

// ----------------------------------------------------------------------------
// B = 8192, K = 512, L = 10752 literals, C = 2688 conj, F = 256
// fp16 mma.sync m16n8k16 GEMM; x@muT folded in as extra N-tiles.
// 128x96 CTA, 256 threads, 3 CTAs/SM (forced 84 regs), 2-stage pipeline.
// ----------------------------------------------------------------------------
#define BATCH   8192
#define KDIM    512
#define LDIM    10752
#define LDIM2   11040        // + 256 mu rows + 32 zero pad (115 tiles exactly)
#define CDIM    2688
#define FDIM    256
#define DPITCH  384

#define BM 128
#define BN 96                // 8 triples = 24 conjunctions (triple-aligned)
#define BK 64
#define NTHREADS 256         // 8 warps: 4 (m) x 2 (n), warp tile 32 x 48
#define STAGE   28672        // (128+96)*128 bytes
#define BOFF    16384
#define SM_BIAS (2 * STAGE)  // 57344
#define SMEM_NEED (SM_BIAS + 384)
#define LPITCH  104
#define NLT     (LDIM / BN)  // 112 literal tiles; bx 112..114 are mu tiles

// scratch
__device__ __half g_A[(size_t)BATCH * KDIM];
__device__ __half g_B[(size_t)LDIM2 * KDIM];
__device__ __half g_conj[(size_t)BATCH * CDIM];
__device__ float g_dot[(size_t)BATCH * DPITCH];
__device__ float g_xn[BATCH];
__device__ float g_mn[FDIM];

// ---------------------------------------------------------------- helpers
__device__ __forceinline__ uint32_t smem_u32(const void* p) {
    uint32_t a;
    asm("{ .reg .u64 t; cvta.to.shared.u64 t, %1; cvt.u32.u64 %0, t; }" : "=r"(a) : "l"(p));
    return a;
}
__device__ __forceinline__ void cp16(uint32_t dst, const void* src) {
    asm volatile("cp.async.cg.shared.global [%0], [%1], 16;" :: "r"(dst), "l"(src) : "memory");
}
#define CP_COMMIT() asm volatile("cp.async.commit_group;" ::: "memory")
#define CP_WAIT(n)  asm volatile("cp.async.wait_group %0;" :: "n"(n) : "memory")

__device__ __forceinline__ void ldsm_x4(uint32_t addr, uint32_t r[4]) {
    asm volatile("ldmatrix.sync.aligned.m8n8.x4.shared.b16 {%0,%1,%2,%3}, [%4];"
        : "=r"(r[0]), "=r"(r[1]), "=r"(r[2]), "=r"(r[3]) : "r"(addr));
}
__device__ __forceinline__ void mma_f16(float c[4], const uint32_t a[4],
                                        uint32_t b0, uint32_t b1) {
    asm volatile("mma.sync.aligned.m16n8k16.row.col.f32.f16.f16.f32 "
        "{%0,%1,%2,%3}, {%4,%5,%6,%7}, {%8,%9}, {%0,%1,%2,%3};"
        : "+f"(c[0]), "+f"(c[1]), "+f"(c[2]), "+f"(c[3])
        : "r"(a[0]), "r"(a[1]), "r"(a[2]), "r"(a[3]), "r"(b0), "r"(b1));
}

__device__ __forceinline__ float fast_tanh(float x) {
    float ax = fabsf(x);
    float t;
    asm("ex2.approx.f32 %0, %1;" : "=f"(t) : "f"(ax * -2.885390082f));
    float r = __fdividef(1.f - t, 1.f + t);
    return copysignf(r, x);
}

// ---------------------------------------------------------------- prep kernels
// merged: blocks 0..1023 -> x conv + ||x||^2; 1024..1055 -> mu; 1056..1059 -> pad
__global__ void prep_misc_kernel(const float* __restrict__ x,
                                 const float* __restrict__ mu) {
    const int tid = threadIdx.x, wid = tid >> 5, lane = tid & 31;
    const int bb = blockIdx.x;
    if (bb < 1024) {
        int row = bb * 8 + wid;
        const float* src = x + (size_t)row * KDIM;
        __half* dst = g_A + (size_t)row * KDIM;
        float sq = 0.f;
#pragma unroll
        for (int j = 0; j < 4; j++) {
            int idx = lane + j * 32;
            float4 v = *(const float4*)(src + idx * 4);
            sq = fmaf(v.x, v.x, sq); sq = fmaf(v.y, v.y, sq);
            sq = fmaf(v.z, v.z, sq); sq = fmaf(v.w, v.w, sq);
            __half2 h0 = __floats2half2_rn(v.x, v.y);
            __half2 h1 = __floats2half2_rn(v.z, v.w);
            *(uint2*)(dst + idx * 4) = make_uint2(*(uint32_t*)&h0, *(uint32_t*)&h1);
        }
#pragma unroll
        for (int off = 16; off > 0; off >>= 1)
            sq += __shfl_xor_sync(0xffffffffu, sq, off);
        if (lane == 0) g_xn[row] = sq;
    } else if (bb < 1056) {
        int f = (bb - 1024) * 8 + wid;
        const float* src = mu + (size_t)f * KDIM;
        __half* dst = g_B + (size_t)(LDIM + f) * KDIM;
        float sq = 0.f;
#pragma unroll
        for (int j = 0; j < 4; j++) {
            int idx = lane + j * 32;
            float4 v = *(const float4*)(src + idx * 4);
            sq = fmaf(v.x, v.x, sq); sq = fmaf(v.y, v.y, sq);
            sq = fmaf(v.z, v.z, sq); sq = fmaf(v.w, v.w, sq);
            __half2 h0 = __floats2half2_rn(v.x, v.y);
            __half2 h1 = __floats2half2_rn(v.z, v.w);
            *(uint2*)(dst + idx * 4) = make_uint2(*(uint32_t*)&h0, *(uint32_t*)&h1);
        }
#pragma unroll
        for (int off = 16; off > 0; off >>= 1)
            sq += __shfl_xor_sync(0xffffffffu, sq, off);
        if (lane == 0) g_mn[f] = sq;
    } else {
        int row = LDIM + FDIM + (bb - 1056) * 8 + wid;   // 11008..11039
        __half* dst = g_B + (size_t)row * KDIM;
#pragma unroll
        for (int j = 0; j < 4; j++) {
            int idx = lane + j * 32;
            *(uint2*)(dst + idx * 4) = make_uint2(0u, 0u);
        }
    }
}

__global__ void prep_w_kernel(const float* __restrict__ w, const float* __restrict__ m) {
    __shared__ float s[32][33];
    int n0 = blockIdx.x * 32, k0 = blockIdx.y * 32;
    int tx = threadIdx.x, ty = threadIdx.y;
    size_t gi = (size_t)(k0 + ty) * LDIM + n0 + tx;
    s[ty][tx] = w[gi] * m[gi];
    __syncthreads();
    g_B[(size_t)(n0 + ty) * KDIM + k0 + tx] = __float2half_rn(s[tx][ty]);
}

// ---------------------------------------------------------------- fused GEMM
__global__ __launch_bounds__(NTHREADS, 3)
void fused_gemm_dnf_kernel(const float* __restrict__ bias) {
    extern __shared__ char smp[];
    const uint32_t sb = smem_u32(smp);

    const int tid = threadIdx.x;
    const int wid = tid >> 5, lane = tid & 31;
    const int bx = blockIdx.x;   // 0..111 literals, 112..114 mu
    const int by = blockIdx.y;
    const int warp_m = wid & 3;
    const int warp_n = wid >> 2;

    float* sbias = (float*)(smp + SM_BIAS);
    if (tid < BN && bx < NLT) sbias[tid] = bias[bx * BN + tid];

    const __half* Ag = g_A + (size_t)(by * BM) * KDIM;
    const __half* Bg = g_B + (size_t)(bx * BN) * KDIM;

    const int r16 = lane & 15, l4 = lane >> 4;
    int am128[2], a7[2];
#pragma unroll
    for (int t = 0; t < 2; t++) {
        int row = warp_m * 32 + t * 16 + r16;
        am128[t] = row * 128; a7[t] = row & 7;
    }
    int bn128[3], b7[3];
#pragma unroll
    for (int i = 0; i < 3; i++) {
        int n = warp_n * 48 + i * 16 + r16;
        bn128[i] = n * 128; b7[i] = n & 7;
    }

    float c[2][6][4];
#pragma unroll
    for (int t = 0; t < 2; t++)
#pragma unroll
        for (int n = 0; n < 6; n++)
#pragma unroll
            for (int e = 0; e < 4; e++) c[t][n][e] = 0.f;

    // A: 128 rows x 8 chunks = 1024 ops (4/thread), B: 96 x 8 = 768 (3/thread)
#define ISSUE(kt)                                                              \
    {                                                                          \
        const uint32_t stA = sb + ((kt) & 1) * STAGE;                          \
        _Pragma("unroll")                                                      \
        for (int j = 0; j < 4; j++) {                                          \
            int idx = tid + NTHREADS * j;                                      \
            int row = idx >> 3, ch = idx & 7;                                  \
            cp16(stA + row * 128 + ((ch ^ (row & 7)) << 4),                    \
                 Ag + (size_t)row * KDIM + (kt) * BK + ch * 8);                \
        }                                                                      \
        _Pragma("unroll")                                                      \
        for (int j = 0; j < 3; j++) {                                          \
            int idx = tid + NTHREADS * j;                                      \
            int row = idx >> 3, ch = idx & 7;                                  \
            cp16(stA + BOFF + row * 128 + ((ch ^ (row & 7)) << 4),             \
                 Bg + (size_t)row * KDIM + (kt) * BK + ch * 8);                \
        }                                                                      \
        CP_COMMIT();                                                           \
    }

    ISSUE(0);

    const int NKT = KDIM / BK;   // 8
#pragma unroll
    for (int kt = 0; kt < NKT; kt++) {
        CP_WAIT(0);
        __syncthreads();           // all warps done reading buffer (kt-1)&1
        if (kt + 1 < NKT) ISSUE(kt + 1);

        const uint32_t sA = sb + (kt & 1) * STAGE;
        const uint32_t sB = sA + BOFF;
#pragma unroll
        for (int ks = 0; ks < 4; ks++) {
            uint32_t af[2][4], bf[3][4];
            const int ch = 2 * ks + l4;
#pragma unroll
            for (int t = 0; t < 2; t++)
                ldsm_x4(sA + am128[t] + ((ch ^ a7[t]) << 4), af[t]);
#pragma unroll
            for (int i = 0; i < 3; i++)
                ldsm_x4(sB + bn128[i] + ((ch ^ b7[i]) << 4), bf[i]);
#pragma unroll
            for (int t = 0; t < 2; t++)
#pragma unroll
                for (int i = 0; i < 3; i++) {
                    mma_f16(c[t][2 * i + 0], af[t], bf[i][0], bf[i][2]);
                    mma_f16(c[t][2 * i + 1], af[t], bf[i][1], bf[i][3]);
                }
        }
    }
#undef ISSUE

    __syncthreads();

    const int g = lane >> 2, cc = lane & 3;

    if (bx >= NLT) {
        // ------------- mu tiles: write raw dots to g_dot -------------
        const int colbase = bx * BN - LDIM;   // 0, 96, 192
        float* dp = g_dot + (size_t)(by * BM) * DPITCH + colbase;
#pragma unroll
        for (int t = 0; t < 2; t++) {
            int row0 = warp_m * 32 + t * 16 + g;
#pragma unroll
            for (int i = 0; i < 3; i++)
#pragma unroll
                for (int j = 0; j < 2; j++) {
                    int colb = warp_n * 48 + i * 16 + j * 8 + 2 * cc;
                    int nt = 2 * i + j;
                    *(float2*)(dp + (size_t)row0 * DPITCH + colb) =
                        make_float2(c[t][nt][0], c[t][nt][1]);
                    *(float2*)(dp + (size_t)(row0 + 8) * DPITCH + colb) =
                        make_float2(c[t][nt][2], c[t][nt][3]);
                }
        }
        return;
    }

    // ---------------- literal epilogue: tanh + conj reduce ----------------
    float* Ls = (float*)smp;   // [128][LPITCH] = 53 KB, fits in 2 stages
#pragma unroll
    for (int t = 0; t < 2; t++) {
        int row0 = warp_m * 32 + t * 16 + g;
#pragma unroll
        for (int i = 0; i < 3; i++)
#pragma unroll
            for (int j = 0; j < 2; j++) {
                int colb = warp_n * 48 + i * 16 + j * 8 + 2 * cc;
                int nt = 2 * i + j;
                float b0 = sbias[colb], b1 = sbias[colb + 1];
                float2 v0, v1;
                v0.x = fast_tanh(c[t][nt][0] + b0);
                v0.y = fast_tanh(c[t][nt][1] + b1);
                v1.x = fast_tanh(c[t][nt][2] + b0);
                v1.y = fast_tanh(c[t][nt][3] + b1);
                *(float2*)(Ls + row0 * LPITCH + colb) = v0;
                *(float2*)(Ls + (row0 + 8) * LPITCH + colb) = v1;
            }
    }
    __syncthreads();

    // 128 rows x 24 conj = 3072 tasks, fp16 output
    for (int t = tid; t < BM * 24; t += NTHREADS) {
        int ci  = t % 24;
        int row = t / 24;
        int tri = ci / 3, p = ci % 3;
        int base = tri * 12 + p * (p + 1);   // 0, 2, 6
        int dep  = 2 * (p + 1);              // 2, 4, 6
        const float* rp = Ls + row * LPITCH + base;
        float s = 0.f;
        for (int qq = 0; qq < dep; qq++) s += rp[qq];
        g_conj[(size_t)(by * BM + row) * CDIM + bx * 24 + ci] =
            __float2half_rn(fast_tanh(s - (float)dep + 1.5f));
    }
}

// ---------------------------------------------------------------- finalize
#define RB 8

__global__ __launch_bounds__(256)
void finalize_kernel(const float* __restrict__ sigma, float* __restrict__ out)
{
    __shared__ __half sc[RB][CDIM];   // 43 KB
    __shared__ float red[8];
    __shared__ float xns[RB];

    const int tid = threadIdx.x;
    const int f   = tid;
    const int r0  = blockIdx.x * RB;
    const int lane = tid & 31, warp = tid >> 5;

#pragma unroll
    for (int r = 0; r < RB; r++) {
        const uint4* src = (const uint4*)(g_conj + (size_t)(r0 + r) * CDIM);
        uint4* dst = (uint4*)sc[r];
        for (int i = tid; i < CDIM / 8; i += 256) dst[i] = src[i];
    }
    if (tid < RB) xns[tid] = g_xn[r0 + tid];

    float dt[RB];
#pragma unroll
    for (int r = 0; r < RB; r++) dt[r] = g_dot[(size_t)(r0 + r) * DPITCH + f];

    const float mn    = g_mn[f];
    const float sig   = sigma[f];
    const float inv2s = 0.5f / (sig * sig);
    const int   g     = f >> 6;
    const int   nconj = 6 + 3 * g;
    const int   cstart = 96 * g * (g + 3) + (f & 63) * nconj;
    __syncthreads();

#pragma unroll
    for (int r = 0; r < RB; r++) {
        float s = 0.f;
        for (int q = 0; q < nconj; q++) s += __half2float(sc[r][cstart + q]);
        float dnnf = fast_tanh(s + (float)nconj - 1.5f);

        float sq = xns[r] - 2.f * dt[r] + mn;
        float logit = 2.0f * expf(-sq * inv2s);
        float e = expf(logit);

        float v = e;
#pragma unroll
        for (int off = 16; off > 0; off >>= 1)
            v += __shfl_xor_sync(0xffffffffu, v, off);
        if (lane == 0) red[warp] = v;
        __syncthreads();
        float tot = red[0] + red[1] + red[2] + red[3] +
                    red[4] + red[5] + red[6] + red[7];
        out[(size_t)(r0 + r) * FDIM + f] = dnnf * (e / tot);
        __syncthreads();
    }
}

// ---------------------------------------------------------------- launch
extern "C" void kernel_launch(void* const* d_in, const int* in_sizes, int n_in,
                              void* d_out, int out_size)
{
    const float* x     = (const float*)d_in[0];
    const float* w     = (const float*)d_in[1];
    const float* msk   = (const float*)d_in[2];
    const float* bias  = (const float*)d_in[3];
    const float* mu    = (const float*)d_in[4];
    const float* sigma = (const float*)d_in[5];
    float* out = (float*)d_out;

    cudaFuncSetAttribute(fused_gemm_dnf_kernel,
                         cudaFuncAttributeMaxDynamicSharedMemorySize, SMEM_NEED);

    prep_misc_kernel<<<1060, 256>>>(x, mu);
    {
        dim3 g(LDIM / 32, KDIM / 32);
        dim3 b(32, 32);
        prep_w_kernel<<<g, b>>>(w, msk);
    }
    {
        dim3 grid(LDIM2 / BN, BATCH / BM);   // (115, 64)
        fused_gemm_dnf_kernel<<<grid, NTHREADS, SMEM_NEED>>>(bias);
    }
    finalize_kernel<<<BATCH / RB, 256>>>(sigma, out);
}

// round 12
// speedup vs baseline: 1.4327x; 1.0053x over previous
#include <cuda_runtime.h>
#include <cuda_fp16.h>
#include <cstdint>

// ----------------------------------------------------------------------------
// B = 8192, K = 512, L = 10752 literals, C = 2688 conj, F = 256
// fp16 mma.sync m16n8k16 GEMM; x@muT folded in as extra N-tiles.
// 128x96 CTA, 256 threads, 3 CTAs/SM, 2-stage pipeline. Direct-read finalize.
// ----------------------------------------------------------------------------
#define BATCH   8192
#define KDIM    512
#define LDIM    10752
#define LDIM2   11040        // + 256 mu rows + 32 zero pad (115 tiles exactly)
#define CDIM    2688
#define FDIM    256
#define DPITCH  384

#define BM 128
#define BN 96                // 8 triples = 24 conjunctions (triple-aligned)
#define BK 64
#define NTHREADS 256         // 8 warps: 4 (m) x 2 (n), warp tile 32 x 48
#define STAGE   28672        // (128+96)*128 bytes
#define BOFF    16384
#define SM_BIAS (2 * STAGE)  // 57344
#define SMEM_NEED (SM_BIAS + 384)
#define LPITCH  104
#define NLT     (LDIM / BN)  // 112 literal tiles; bx 112..114 are mu tiles

// scratch
__device__ __half g_A[(size_t)BATCH * KDIM];
__device__ __half g_B[(size_t)LDIM2 * KDIM];
__device__ __half g_conj[(size_t)BATCH * CDIM];
__device__ float g_dot[(size_t)BATCH * DPITCH];
__device__ float g_xn[BATCH];
__device__ float g_mn[FDIM];

// ---------------------------------------------------------------- helpers
__device__ __forceinline__ uint32_t smem_u32(const void* p) {
    uint32_t a;
    asm("{ .reg .u64 t; cvta.to.shared.u64 t, %1; cvt.u32.u64 %0, t; }" : "=r"(a) : "l"(p));
    return a;
}
__device__ __forceinline__ void cp16(uint32_t dst, const void* src) {
    asm volatile("cp.async.cg.shared.global [%0], [%1], 16;" :: "r"(dst), "l"(src) : "memory");
}
#define CP_COMMIT() asm volatile("cp.async.commit_group;" ::: "memory")
#define CP_WAIT(n)  asm volatile("cp.async.wait_group %0;" :: "n"(n) : "memory")

__device__ __forceinline__ void ldsm_x4(uint32_t addr, uint32_t r[4]) {
    asm volatile("ldmatrix.sync.aligned.m8n8.x4.shared.b16 {%0,%1,%2,%3}, [%4];"
        : "=r"(r[0]), "=r"(r[1]), "=r"(r[2]), "=r"(r[3]) : "r"(addr));
}
__device__ __forceinline__ void mma_f16(float c[4], const uint32_t a[4],
                                        uint32_t b0, uint32_t b1) {
    asm volatile("mma.sync.aligned.m16n8k16.row.col.f32.f16.f16.f32 "
        "{%0,%1,%2,%3}, {%4,%5,%6,%7}, {%8,%9}, {%0,%1,%2,%3};"
        : "+f"(c[0]), "+f"(c[1]), "+f"(c[2]), "+f"(c[3])
        : "r"(a[0]), "r"(a[1]), "r"(a[2]), "r"(a[3]), "r"(b0), "r"(b1));
}

__device__ __forceinline__ float fast_tanh(float x) {
    float ax = fabsf(x);
    float t;
    asm("ex2.approx.f32 %0, %1;" : "=f"(t) : "f"(ax * -2.885390082f));
    float r = __fdividef(1.f - t, 1.f + t);
    return copysignf(r, x);
}

// ---------------------------------------------------------------- prep kernels
// merged: blocks 0..1023 -> x conv + ||x||^2; 1024..1055 -> mu; 1056..1059 -> pad
__global__ void prep_misc_kernel(const float* __restrict__ x,
                                 const float* __restrict__ mu) {
    const int tid = threadIdx.x, wid = tid >> 5, lane = tid & 31;
    const int bb = blockIdx.x;
    if (bb < 1024) {
        int row = bb * 8 + wid;
        const float* src = x + (size_t)row * KDIM;
        __half* dst = g_A + (size_t)row * KDIM;
        float sq = 0.f;
#pragma unroll
        for (int j = 0; j < 4; j++) {
            int idx = lane + j * 32;
            float4 v = *(const float4*)(src + idx * 4);
            sq = fmaf(v.x, v.x, sq); sq = fmaf(v.y, v.y, sq);
            sq = fmaf(v.z, v.z, sq); sq = fmaf(v.w, v.w, sq);
            __half2 h0 = __floats2half2_rn(v.x, v.y);
            __half2 h1 = __floats2half2_rn(v.z, v.w);
            *(uint2*)(dst + idx * 4) = make_uint2(*(uint32_t*)&h0, *(uint32_t*)&h1);
        }
#pragma unroll
        for (int off = 16; off > 0; off >>= 1)
            sq += __shfl_xor_sync(0xffffffffu, sq, off);
        if (lane == 0) g_xn[row] = sq;
    } else if (bb < 1056) {
        int f = (bb - 1024) * 8 + wid;
        const float* src = mu + (size_t)f * KDIM;
        __half* dst = g_B + (size_t)(LDIM + f) * KDIM;
        float sq = 0.f;
#pragma unroll
        for (int j = 0; j < 4; j++) {
            int idx = lane + j * 32;
            float4 v = *(const float4*)(src + idx * 4);
            sq = fmaf(v.x, v.x, sq); sq = fmaf(v.y, v.y, sq);
            sq = fmaf(v.z, v.z, sq); sq = fmaf(v.w, v.w, sq);
            __half2 h0 = __floats2half2_rn(v.x, v.y);
            __half2 h1 = __floats2half2_rn(v.z, v.w);
            *(uint2*)(dst + idx * 4) = make_uint2(*(uint32_t*)&h0, *(uint32_t*)&h1);
        }
#pragma unroll
        for (int off = 16; off > 0; off >>= 1)
            sq += __shfl_xor_sync(0xffffffffu, sq, off);
        if (lane == 0) g_mn[f] = sq;
    } else {
        int row = LDIM + FDIM + (bb - 1056) * 8 + wid;   // 11008..11039
        __half* dst = g_B + (size_t)row * KDIM;
#pragma unroll
        for (int j = 0; j < 4; j++) {
            int idx = lane + j * 32;
            *(uint2*)(dst + idx * 4) = make_uint2(0u, 0u);
        }
    }
}

__global__ void prep_w_kernel(const float* __restrict__ w, const float* __restrict__ m) {
    __shared__ float s[32][33];
    int n0 = blockIdx.x * 32, k0 = blockIdx.y * 32;
    int tx = threadIdx.x, ty = threadIdx.y;
    size_t gi = (size_t)(k0 + ty) * LDIM + n0 + tx;
    s[ty][tx] = w[gi] * m[gi];
    __syncthreads();
    g_B[(size_t)(n0 + ty) * KDIM + k0 + tx] = __float2half_rn(s[tx][ty]);
}

// ---------------------------------------------------------------- fused GEMM
__global__ __launch_bounds__(NTHREADS, 3)
void fused_gemm_dnf_kernel(const float* __restrict__ bias) {
    extern __shared__ char smp[];
    const uint32_t sb = smem_u32(smp);

    const int tid = threadIdx.x;
    const int wid = tid >> 5, lane = tid & 31;
    const int bx = blockIdx.x;   // 0..111 literals, 112..114 mu
    const int by = blockIdx.y;
    const int warp_m = wid & 3;
    const int warp_n = wid >> 2;

    float* sbias = (float*)(smp + SM_BIAS);
    if (tid < BN && bx < NLT) sbias[tid] = bias[bx * BN + tid];

    const __half* Ag = g_A + (size_t)(by * BM) * KDIM;
    const __half* Bg = g_B + (size_t)(bx * BN) * KDIM;

    const int r16 = lane & 15, l4 = lane >> 4;
    int am128[2], a7[2];
#pragma unroll
    for (int t = 0; t < 2; t++) {
        int row = warp_m * 32 + t * 16 + r16;
        am128[t] = row * 128; a7[t] = row & 7;
    }
    int bn128[3], b7[3];
#pragma unroll
    for (int i = 0; i < 3; i++) {
        int n = warp_n * 48 + i * 16 + r16;
        bn128[i] = n * 128; b7[i] = n & 7;
    }

    float c[2][6][4];
#pragma unroll
    for (int t = 0; t < 2; t++)
#pragma unroll
        for (int n = 0; n < 6; n++)
#pragma unroll
            for (int e = 0; e < 4; e++) c[t][n][e] = 0.f;

    // A: 128 rows x 8 chunks = 1024 ops (4/thread), B: 96 x 8 = 768 (3/thread)
#define ISSUE(kt)                                                              \
    {                                                                          \
        const uint32_t stA = sb + ((kt) & 1) * STAGE;                          \
        _Pragma("unroll")                                                      \
        for (int j = 0; j < 4; j++) {                                          \
            int idx = tid + NTHREADS * j;                                      \
            int row = idx >> 3, ch = idx & 7;                                  \
            cp16(stA + row * 128 + ((ch ^ (row & 7)) << 4),                    \
                 Ag + (size_t)row * KDIM + (kt) * BK + ch * 8);                \
        }                                                                      \
        _Pragma("unroll")                                                      \
        for (int j = 0; j < 3; j++) {                                          \
            int idx = tid + NTHREADS * j;                                      \
            int row = idx >> 3, ch = idx & 7;                                  \
            cp16(stA + BOFF + row * 128 + ((ch ^ (row & 7)) << 4),             \
                 Bg + (size_t)row * KDIM + (kt) * BK + ch * 8);                \
        }                                                                      \
        CP_COMMIT();                                                           \
    }

    ISSUE(0);

    const int NKT = KDIM / BK;   // 8
#pragma unroll
    for (int kt = 0; kt < NKT; kt++) {
        CP_WAIT(0);
        __syncthreads();           // all warps done reading other buffer
        if (kt + 1 < NKT) ISSUE(kt + 1);

        const uint32_t sA = sb + (kt & 1) * STAGE;
        const uint32_t sB = sA + BOFF;
#pragma unroll
        for (int ks = 0; ks < 4; ks++) {
            uint32_t af[2][4], bf[3][4];
            const int ch = 2 * ks + l4;
#pragma unroll
            for (int t = 0; t < 2; t++)
                ldsm_x4(sA + am128[t] + ((ch ^ a7[t]) << 4), af[t]);
#pragma unroll
            for (int i = 0; i < 3; i++)
                ldsm_x4(sB + bn128[i] + ((ch ^ b7[i]) << 4), bf[i]);
#pragma unroll
            for (int t = 0; t < 2; t++)
#pragma unroll
                for (int i = 0; i < 3; i++) {
                    mma_f16(c[t][2 * i + 0], af[t], bf[i][0], bf[i][2]);
                    mma_f16(c[t][2 * i + 1], af[t], bf[i][1], bf[i][3]);
                }
        }
    }
#undef ISSUE

    __syncthreads();

    const int g = lane >> 2, cc = lane & 3;

    if (bx >= NLT) {
        // ------------- mu tiles: write raw dots to g_dot -------------
        const int colbase = bx * BN - LDIM;   // 0, 96, 192
        float* dp = g_dot + (size_t)(by * BM) * DPITCH + colbase;
#pragma unroll
        for (int t = 0; t < 2; t++) {
            int row0 = warp_m * 32 + t * 16 + g;
#pragma unroll
            for (int i = 0; i < 3; i++)
#pragma unroll
                for (int j = 0; j < 2; j++) {
                    int colb = warp_n * 48 + i * 16 + j * 8 + 2 * cc;
                    int nt = 2 * i + j;
                    *(float2*)(dp + (size_t)row0 * DPITCH + colb) =
                        make_float2(c[t][nt][0], c[t][nt][1]);
                    *(float2*)(dp + (size_t)(row0 + 8) * DPITCH + colb) =
                        make_float2(c[t][nt][2], c[t][nt][3]);
                }
        }
        return;
    }

    // ---------------- literal epilogue: tanh + conj reduce ----------------
    float* Ls = (float*)smp;   // [128][LPITCH] = 53 KB, fits in 2 stages
#pragma unroll
    for (int t = 0; t < 2; t++) {
        int row0 = warp_m * 32 + t * 16 + g;
#pragma unroll
        for (int i = 0; i < 3; i++)
#pragma unroll
            for (int j = 0; j < 2; j++) {
                int colb = warp_n * 48 + i * 16 + j * 8 + 2 * cc;
                int nt = 2 * i + j;
                float b0 = sbias[colb], b1 = sbias[colb + 1];
                float2 v0, v1;
                v0.x = fast_tanh(c[t][nt][0] + b0);
                v0.y = fast_tanh(c[t][nt][1] + b1);
                v1.x = fast_tanh(c[t][nt][2] + b0);
                v1.y = fast_tanh(c[t][nt][3] + b1);
                *(float2*)(Ls + row0 * LPITCH + colb) = v0;
                *(float2*)(Ls + (row0 + 8) * LPITCH + colb) = v1;
            }
    }
    __syncthreads();

    // 128 rows x 24 conj = 3072 tasks, fp16 output
    for (int t = tid; t < BM * 24; t += NTHREADS) {
        int ci  = t % 24;
        int row = t / 24;
        int tri = ci / 3, p = ci % 3;
        int base = tri * 12 + p * (p + 1);   // 0, 2, 6
        int dep  = 2 * (p + 1);              // 2, 4, 6
        const float* rp = Ls + row * LPITCH + base;
        float s = 0.f;
        for (int qq = 0; qq < dep; qq++) s += rp[qq];
        g_conj[(size_t)(by * BM + row) * CDIM + bx * 24 + ci] =
            __float2half_rn(fast_tanh(s - (float)dep + 1.5f));
    }
}

// ---------------------------------------------------------------- finalize
// Direct-read: conj segments are disjoint per formula; no smem staging.
#define RB 8

__global__ __launch_bounds__(256)
void finalize_kernel(const float* __restrict__ sigma, float* __restrict__ out)
{
    __shared__ float red[8];
    __shared__ float xns[RB];

    const int tid = threadIdx.x;
    const int f   = tid;
    const int r0  = blockIdx.x * RB;
    const int lane = tid & 31, warp = tid >> 5;

    if (tid < RB) xns[tid] = g_xn[r0 + tid];

    float dt[RB];
#pragma unroll
    for (int r = 0; r < RB; r++) dt[r] = g_dot[(size_t)(r0 + r) * DPITCH + f];

    const float mn    = g_mn[f];
    const float sig   = sigma[f];
    const float inv2s = 0.5f / (sig * sig);
    const int   g     = f >> 6;
    const int   nconj = 6 + 3 * g;
    const int   cstart = 96 * g * (g + 3) + (f & 63) * nconj;
    __syncthreads();

#pragma unroll
    for (int r = 0; r < RB; r++) {
        const __half* cp = g_conj + (size_t)(r0 + r) * CDIM + cstart;
        float s = 0.f;
        for (int q = 0; q < nconj; q++) s += __half2float(__ldg(cp + q));
        float dnnf = fast_tanh(s + (float)nconj - 1.5f);

        float sq = xns[r] - 2.f * dt[r] + mn;
        float logit = 2.0f * expf(-sq * inv2s);
        float e = expf(logit);

        float v = e;
#pragma unroll
        for (int off = 16; off > 0; off >>= 1)
            v += __shfl_xor_sync(0xffffffffu, v, off);
        if (lane == 0) red[warp] = v;
        __syncthreads();
        float tot = red[0] + red[1] + red[2] + red[3] +
                    red[4] + red[5] + red[6] + red[7];
        out[(size_t)(r0 + r) * FDIM + f] = dnnf * (e / tot);
        __syncthreads();
    }
}

// ---------------------------------------------------------------- launch
extern "C" void kernel_launch(void* const* d_in, const int* in_sizes, int n_in,
                              void* d_out, int out_size)
{
    const float* x     = (const float*)d_in[0];
    const float* w     = (const float*)d_in[1];
    const float* msk   = (const float*)d_in[2];
    const float* bias  = (const float*)d_in[3];
    const float* mu    = (const float*)d_in[4];
    const float* sigma = (const float*)d_in[5];
    float* out = (float*)d_out;

    cudaFuncSetAttribute(fused_gemm_dnf_kernel,
                         cudaFuncAttributeMaxDynamicSharedMemorySize, SMEM_NEED);

    prep_misc_kernel<<<1060, 256>>>(x, mu);
    {
        dim3 g(LDIM / 32, KDIM / 32);
        dim3 b(32, 32);
        prep_w_kernel<<<g, b>>>(w, msk);
    }
    {
        dim3 grid(LDIM2 / BN, BATCH / BM);   // (115, 64)
        fused_gemm_dnf_kernel<<<grid, NTHREADS, SMEM_NEED>>>(bias);
    }
    finalize_kernel<<<BATCH / RB, 256>>>(sigma, out);
}

// round 13
// speedup vs baseline: 1.4557x; 1.0161x over previous
#include <cuda_runtime.h>
#include <cuda_fp16.h>
#include <cstdint>

// ----------------------------------------------------------------------------
// B = 8192, K = 512, L = 10752 literals, C = 2688 conj, F = 256
// fp16 mma.sync m16n8k16 GEMM; x@muT folded in as extra N-tiles.
// 128x96 CTA, 256 threads, 3 CTAs/SM, 2-stage pipeline.
// Finalize: vectorized half2 conj reads + single-barrier softmax.
// ----------------------------------------------------------------------------
#define BATCH   8192
#define KDIM    512
#define LDIM    10752
#define LDIM2   11040        // + 256 mu rows + 32 zero pad (115 tiles exactly)
#define CDIM    2688
#define FDIM    256
#define DPITCH  384

#define BM 128
#define BN 96                // 8 triples = 24 conjunctions (triple-aligned)
#define BK 64
#define NTHREADS 256         // 8 warps: 4 (m) x 2 (n), warp tile 32 x 48
#define STAGE   28672        // (128+96)*128 bytes
#define BOFF    16384
#define SM_BIAS (2 * STAGE)  // 57344
#define SMEM_NEED (SM_BIAS + 384)
#define LPITCH  104
#define NLT     (LDIM / BN)  // 112 literal tiles; bx 112..114 are mu tiles

// scratch
__device__ __half g_A[(size_t)BATCH * KDIM];
__device__ __half g_B[(size_t)LDIM2 * KDIM];
__device__ __half g_conj[(size_t)BATCH * CDIM];
__device__ float g_dot[(size_t)BATCH * DPITCH];
__device__ float g_xn[BATCH];
__device__ float g_mn[FDIM];

// ---------------------------------------------------------------- helpers
__device__ __forceinline__ uint32_t smem_u32(const void* p) {
    uint32_t a;
    asm("{ .reg .u64 t; cvta.to.shared.u64 t, %1; cvt.u32.u64 %0, t; }" : "=r"(a) : "l"(p));
    return a;
}
__device__ __forceinline__ void cp16(uint32_t dst, const void* src) {
    asm volatile("cp.async.cg.shared.global [%0], [%1], 16;" :: "r"(dst), "l"(src) : "memory");
}
#define CP_COMMIT() asm volatile("cp.async.commit_group;" ::: "memory")
#define CP_WAIT(n)  asm volatile("cp.async.wait_group %0;" :: "n"(n) : "memory")

__device__ __forceinline__ void ldsm_x4(uint32_t addr, uint32_t r[4]) {
    asm volatile("ldmatrix.sync.aligned.m8n8.x4.shared.b16 {%0,%1,%2,%3}, [%4];"
        : "=r"(r[0]), "=r"(r[1]), "=r"(r[2]), "=r"(r[3]) : "r"(addr));
}
__device__ __forceinline__ void mma_f16(float c[4], const uint32_t a[4],
                                        uint32_t b0, uint32_t b1) {
    asm volatile("mma.sync.aligned.m16n8k16.row.col.f32.f16.f16.f32 "
        "{%0,%1,%2,%3}, {%4,%5,%6,%7}, {%8,%9}, {%0,%1,%2,%3};"
        : "+f"(c[0]), "+f"(c[1]), "+f"(c[2]), "+f"(c[3])
        : "r"(a[0]), "r"(a[1]), "r"(a[2]), "r"(a[3]), "r"(b0), "r"(b1));
}

__device__ __forceinline__ float fast_tanh(float x) {
    float ax = fabsf(x);
    float t;
    asm("ex2.approx.f32 %0, %1;" : "=f"(t) : "f"(ax * -2.885390082f));
    float r = __fdividef(1.f - t, 1.f + t);
    return copysignf(r, x);
}

// ---------------------------------------------------------------- prep kernels
__global__ void prep_misc_kernel(const float* __restrict__ x,
                                 const float* __restrict__ mu) {
    const int tid = threadIdx.x, wid = tid >> 5, lane = tid & 31;
    const int bb = blockIdx.x;
    if (bb < 1024) {
        int row = bb * 8 + wid;
        const float* src = x + (size_t)row * KDIM;
        __half* dst = g_A + (size_t)row * KDIM;
        float sq = 0.f;
#pragma unroll
        for (int j = 0; j < 4; j++) {
            int idx = lane + j * 32;
            float4 v = *(const float4*)(src + idx * 4);
            sq = fmaf(v.x, v.x, sq); sq = fmaf(v.y, v.y, sq);
            sq = fmaf(v.z, v.z, sq); sq = fmaf(v.w, v.w, sq);
            __half2 h0 = __floats2half2_rn(v.x, v.y);
            __half2 h1 = __floats2half2_rn(v.z, v.w);
            *(uint2*)(dst + idx * 4) = make_uint2(*(uint32_t*)&h0, *(uint32_t*)&h1);
        }
#pragma unroll
        for (int off = 16; off > 0; off >>= 1)
            sq += __shfl_xor_sync(0xffffffffu, sq, off);
        if (lane == 0) g_xn[row] = sq;
    } else if (bb < 1056) {
        int f = (bb - 1024) * 8 + wid;
        const float* src = mu + (size_t)f * KDIM;
        __half* dst = g_B + (size_t)(LDIM + f) * KDIM;
        float sq = 0.f;
#pragma unroll
        for (int j = 0; j < 4; j++) {
            int idx = lane + j * 32;
            float4 v = *(const float4*)(src + idx * 4);
            sq = fmaf(v.x, v.x, sq); sq = fmaf(v.y, v.y, sq);
            sq = fmaf(v.z, v.z, sq); sq = fmaf(v.w, v.w, sq);
            __half2 h0 = __floats2half2_rn(v.x, v.y);
            __half2 h1 = __floats2half2_rn(v.z, v.w);
            *(uint2*)(dst + idx * 4) = make_uint2(*(uint32_t*)&h0, *(uint32_t*)&h1);
        }
#pragma unroll
        for (int off = 16; off > 0; off >>= 1)
            sq += __shfl_xor_sync(0xffffffffu, sq, off);
        if (lane == 0) g_mn[f] = sq;
    } else {
        int row = LDIM + FDIM + (bb - 1056) * 8 + wid;   // 11008..11039
        __half* dst = g_B + (size_t)row * KDIM;
#pragma unroll
        for (int j = 0; j < 4; j++) {
            int idx = lane + j * 32;
            *(uint2*)(dst + idx * 4) = make_uint2(0u, 0u);
        }
    }
}

__global__ void prep_w_kernel(const float* __restrict__ w, const float* __restrict__ m) {
    __shared__ float s[32][33];
    int n0 = blockIdx.x * 32, k0 = blockIdx.y * 32;
    int tx = threadIdx.x, ty = threadIdx.y;
    size_t gi = (size_t)(k0 + ty) * LDIM + n0 + tx;
    s[ty][tx] = w[gi] * m[gi];
    __syncthreads();
    g_B[(size_t)(n0 + ty) * KDIM + k0 + tx] = __float2half_rn(s[tx][ty]);
}

// ---------------------------------------------------------------- fused GEMM
__global__ __launch_bounds__(NTHREADS, 3)
void fused_gemm_dnf_kernel(const float* __restrict__ bias) {
    extern __shared__ char smp[];
    const uint32_t sb = smem_u32(smp);

    const int tid = threadIdx.x;
    const int wid = tid >> 5, lane = tid & 31;
    const int bx = blockIdx.x;   // 0..111 literals, 112..114 mu
    const int by = blockIdx.y;
    const int warp_m = wid & 3;
    const int warp_n = wid >> 2;

    float* sbias = (float*)(smp + SM_BIAS);
    if (tid < BN && bx < NLT) sbias[tid] = bias[bx * BN + tid];

    const __half* Ag = g_A + (size_t)(by * BM) * KDIM;
    const __half* Bg = g_B + (size_t)(bx * BN) * KDIM;

    const int r16 = lane & 15, l4 = lane >> 4;
    int am128[2], a7[2];
#pragma unroll
    for (int t = 0; t < 2; t++) {
        int row = warp_m * 32 + t * 16 + r16;
        am128[t] = row * 128; a7[t] = row & 7;
    }
    int bn128[3], b7[3];
#pragma unroll
    for (int i = 0; i < 3; i++) {
        int n = warp_n * 48 + i * 16 + r16;
        bn128[i] = n * 128; b7[i] = n & 7;
    }

    float c[2][6][4];
#pragma unroll
    for (int t = 0; t < 2; t++)
#pragma unroll
        for (int n = 0; n < 6; n++)
#pragma unroll
            for (int e = 0; e < 4; e++) c[t][n][e] = 0.f;

#define ISSUE(kt)                                                              \
    {                                                                          \
        const uint32_t stA = sb + ((kt) & 1) * STAGE;                          \
        _Pragma("unroll")                                                      \
        for (int j = 0; j < 4; j++) {                                          \
            int idx = tid + NTHREADS * j;                                      \
            int row = idx >> 3, ch = idx & 7;                                  \
            cp16(stA + row * 128 + ((ch ^ (row & 7)) << 4),                    \
                 Ag + (size_t)row * KDIM + (kt) * BK + ch * 8);                \
        }                                                                      \
        _Pragma("unroll")                                                      \
        for (int j = 0; j < 3; j++) {                                          \
            int idx = tid + NTHREADS * j;                                      \
            int row = idx >> 3, ch = idx & 7;                                  \
            cp16(stA + BOFF + row * 128 + ((ch ^ (row & 7)) << 4),             \
                 Bg + (size_t)row * KDIM + (kt) * BK + ch * 8);                \
        }                                                                      \
        CP_COMMIT();                                                           \
    }

    ISSUE(0);

    const int NKT = KDIM / BK;   // 8
#pragma unroll
    for (int kt = 0; kt < NKT; kt++) {
        CP_WAIT(0);
        __syncthreads();
        if (kt + 1 < NKT) ISSUE(kt + 1);

        const uint32_t sA = sb + (kt & 1) * STAGE;
        const uint32_t sB = sA + BOFF;
#pragma unroll
        for (int ks = 0; ks < 4; ks++) {
            uint32_t af[2][4], bf[3][4];
            const int ch = 2 * ks + l4;
#pragma unroll
            for (int t = 0; t < 2; t++)
                ldsm_x4(sA + am128[t] + ((ch ^ a7[t]) << 4), af[t]);
#pragma unroll
            for (int i = 0; i < 3; i++)
                ldsm_x4(sB + bn128[i] + ((ch ^ b7[i]) << 4), bf[i]);
#pragma unroll
            for (int t = 0; t < 2; t++)
#pragma unroll
                for (int i = 0; i < 3; i++) {
                    mma_f16(c[t][2 * i + 0], af[t], bf[i][0], bf[i][2]);
                    mma_f16(c[t][2 * i + 1], af[t], bf[i][1], bf[i][3]);
                }
        }
    }
#undef ISSUE

    __syncthreads();

    const int g = lane >> 2, cc = lane & 3;

    if (bx >= NLT) {
        const int colbase = bx * BN - LDIM;   // 0, 96, 192
        float* dp = g_dot + (size_t)(by * BM) * DPITCH + colbase;
#pragma unroll
        for (int t = 0; t < 2; t++) {
            int row0 = warp_m * 32 + t * 16 + g;
#pragma unroll
            for (int i = 0; i < 3; i++)
#pragma unroll
                for (int j = 0; j < 2; j++) {
                    int colb = warp_n * 48 + i * 16 + j * 8 + 2 * cc;
                    int nt = 2 * i + j;
                    *(float2*)(dp + (size_t)row0 * DPITCH + colb) =
                        make_float2(c[t][nt][0], c[t][nt][1]);
                    *(float2*)(dp + (size_t)(row0 + 8) * DPITCH + colb) =
                        make_float2(c[t][nt][2], c[t][nt][3]);
                }
        }
        return;
    }

    // ---------------- literal epilogue: tanh + conj reduce ----------------
    float* Ls = (float*)smp;   // [128][LPITCH] = 53 KB, fits in 2 stages
#pragma unroll
    for (int t = 0; t < 2; t++) {
        int row0 = warp_m * 32 + t * 16 + g;
#pragma unroll
        for (int i = 0; i < 3; i++)
#pragma unroll
            for (int j = 0; j < 2; j++) {
                int colb = warp_n * 48 + i * 16 + j * 8 + 2 * cc;
                int nt = 2 * i + j;
                float b0 = sbias[colb], b1 = sbias[colb + 1];
                float2 v0, v1;
                v0.x = fast_tanh(c[t][nt][0] + b0);
                v0.y = fast_tanh(c[t][nt][1] + b1);
                v1.x = fast_tanh(c[t][nt][2] + b0);
                v1.y = fast_tanh(c[t][nt][3] + b1);
                *(float2*)(Ls + row0 * LPITCH + colb) = v0;
                *(float2*)(Ls + (row0 + 8) * LPITCH + colb) = v1;
            }
    }
    __syncthreads();

    for (int t = tid; t < BM * 24; t += NTHREADS) {
        int ci  = t % 24;
        int row = t / 24;
        int tri = ci / 3, p = ci % 3;
        int base = tri * 12 + p * (p + 1);   // 0, 2, 6
        int dep  = 2 * (p + 1);              // 2, 4, 6
        const float* rp = Ls + row * LPITCH + base;
        float s = 0.f;
        for (int qq = 0; qq < dep; qq++) s += rp[qq];
        g_conj[(size_t)(by * BM + row) * CDIM + bx * 24 + ci] =
            __float2half_rn(fast_tanh(s - (float)dep + 1.5f));
    }
}

// ---------------------------------------------------------------- finalize
// Vectorized half2 conj reads; one barrier for all 8 rows' softmax.
#define RB 8

__device__ __forceinline__ float h2sum(__half2 v) {
    float2 f = __half22float2(v);
    return f.x + f.y;
}

__global__ __launch_bounds__(256)
void finalize_kernel(const float* __restrict__ sigma, float* __restrict__ out)
{
    __shared__ float red[8][RB + 1];   // [warp][row], padded
    __shared__ float xns[RB];

    const int tid = threadIdx.x;
    const int f   = tid;
    const int r0  = blockIdx.x * RB;
    const int lane = tid & 31, warp = tid >> 5;

    if (tid < RB) xns[tid] = g_xn[r0 + tid];

    float dt[RB];
#pragma unroll
    for (int r = 0; r < RB; r++) dt[r] = g_dot[(size_t)(r0 + r) * DPITCH + f];

    const float mn    = g_mn[f];
    const float sig   = sigma[f];
    const float inv2s = 0.5f / (sig * sig);
    const int   g     = f >> 6;
    const int   nconj = 6 + 3 * g;
    const int   cstart = 96 * g * (g + 3) + (f & 63) * nconj;
    const int   odd   = cstart & 1;
    __syncthreads();   // xns ready

    float dnnf[RB], ev[RB];
#pragma unroll
    for (int r = 0; r < RB; r++) {
        const __half* cp = g_conj + (size_t)(r0 + r) * CDIM + cstart;
        float s = 0.f;
        if (g == 0) {            // 6 conj, cstart always even
            const __half2* p = (const __half2*)cp;
#pragma unroll
            for (int q = 0; q < 3; q++) s += h2sum(__ldg(p + q));
        } else if (g == 2) {     // 12 conj, even
            const __half2* p = (const __half2*)cp;
#pragma unroll
            for (int q = 0; q < 6; q++) s += h2sum(__ldg(p + q));
        } else if (g == 1) {     // 9 conj
            const __half2* p = (const __half2*)(cp + odd);
#pragma unroll
            for (int q = 0; q < 4; q++) s += h2sum(__ldg(p + q));
            s += __half2float(__ldg(odd ? cp : cp + 8));
        } else {                 // 15 conj
            const __half2* p = (const __half2*)(cp + odd);
#pragma unroll
            for (int q = 0; q < 7; q++) s += h2sum(__ldg(p + q));
            s += __half2float(__ldg(odd ? cp : cp + 14));
        }
        dnnf[r] = fast_tanh(s + (float)nconj - 1.5f);

        float sq = xns[r] - 2.f * dt[r] + mn;
        float logit = 2.0f * expf(-sq * inv2s);
        ev[r] = expf(logit);

        float v = ev[r];
#pragma unroll
        for (int off = 16; off > 0; off >>= 1)
            v += __shfl_xor_sync(0xffffffffu, v, off);
        if (lane == 0) red[warp][r] = v;
    }
    __syncthreads();   // single barrier

#pragma unroll
    for (int r = 0; r < RB; r++) {
        float tot = red[0][r] + red[1][r] + red[2][r] + red[3][r] +
                    red[4][r] + red[5][r] + red[6][r] + red[7][r];
        out[(size_t)(r0 + r) * FDIM + f] = dnnf[r] * (ev[r] / tot);
    }
}

// ---------------------------------------------------------------- launch
extern "C" void kernel_launch(void* const* d_in, const int* in_sizes, int n_in,
                              void* d_out, int out_size)
{
    const float* x     = (const float*)d_in[0];
    const float* w     = (const float*)d_in[1];
    const float* msk   = (const float*)d_in[2];
    const float* bias  = (const float*)d_in[3];
    const float* mu    = (const float*)d_in[4];
    const float* sigma = (const float*)d_in[5];
    float* out = (float*)d_out;

    cudaFuncSetAttribute(fused_gemm_dnf_kernel,
                         cudaFuncAttributeMaxDynamicSharedMemorySize, SMEM_NEED);

    prep_misc_kernel<<<1060, 256>>>(x, mu);
    {
        dim3 g(LDIM / 32, KDIM / 32);
        dim3 b(32, 32);
        prep_w_kernel<<<g, b>>>(w, msk);
    }
    {
        dim3 grid(LDIM2 / BN, BATCH / BM);   // (115, 64)
        fused_gemm_dnf_kernel<<<grid, NTHREADS, SMEM_NEED>>>(bias);
    }
    finalize_kernel<<<BATCH / RB, 256>>>(sigma, out);
}

// round 14
// speedup vs baseline: 1.4865x; 1.0212x over previous
#include <cuda_runtime.h>
#include <cuda_fp16.h>
#include <cstdint>

// ----------------------------------------------------------------------------
// B = 8192, K = 512, L = 10752 literals, C = 2688 conj, F = 256
// fp16 mma.sync m16n8k16 GEMM; x@muT folded in as extra N-tiles.
// 128x96 CTA, 256 threads, 3 CTAs/SM, 2-stage pipeline.
// Single merged prep kernel; RB=16 vectorized finalize.
// ----------------------------------------------------------------------------
#define BATCH   8192
#define KDIM    512
#define LDIM    10752
#define LDIM2   11040        // + 256 mu rows + 32 zero pad (115 tiles exactly)
#define CDIM    2688
#define FDIM    256
#define DPITCH  384

#define BM 128
#define BN 96                // 8 triples = 24 conjunctions (triple-aligned)
#define BK 64
#define NTHREADS 256         // 8 warps: 4 (m) x 2 (n), warp tile 32 x 48
#define STAGE   28672        // (128+96)*128 bytes
#define BOFF    16384
#define SM_BIAS (2 * STAGE)  // 57344
#define SMEM_NEED (SM_BIAS + 384)
#define LPITCH  104
#define NLT     (LDIM / BN)  // 112 literal tiles; bx 112..114 are mu tiles

#define NWBLK   (336 * 16)   // 5376 w-transpose tiles

// scratch
__device__ __half g_A[(size_t)BATCH * KDIM];
__device__ __half g_B[(size_t)LDIM2 * KDIM];
__device__ __half g_conj[(size_t)BATCH * CDIM];
__device__ float g_dot[(size_t)BATCH * DPITCH];
__device__ float g_xn[BATCH];
__device__ float g_mn[FDIM];

// ---------------------------------------------------------------- helpers
__device__ __forceinline__ uint32_t smem_u32(const void* p) {
    uint32_t a;
    asm("{ .reg .u64 t; cvta.to.shared.u64 t, %1; cvt.u32.u64 %0, t; }" : "=r"(a) : "l"(p));
    return a;
}
__device__ __forceinline__ void cp16(uint32_t dst, const void* src) {
    asm volatile("cp.async.cg.shared.global [%0], [%1], 16;" :: "r"(dst), "l"(src) : "memory");
}
#define CP_COMMIT() asm volatile("cp.async.commit_group;" ::: "memory")
#define CP_WAIT(n)  asm volatile("cp.async.wait_group %0;" :: "n"(n) : "memory")

__device__ __forceinline__ void ldsm_x4(uint32_t addr, uint32_t r[4]) {
    asm volatile("ldmatrix.sync.aligned.m8n8.x4.shared.b16 {%0,%1,%2,%3}, [%4];"
        : "=r"(r[0]), "=r"(r[1]), "=r"(r[2]), "=r"(r[3]) : "r"(addr));
}
__device__ __forceinline__ void mma_f16(float c[4], const uint32_t a[4],
                                        uint32_t b0, uint32_t b1) {
    asm volatile("mma.sync.aligned.m16n8k16.row.col.f32.f16.f16.f32 "
        "{%0,%1,%2,%3}, {%4,%5,%6,%7}, {%8,%9}, {%0,%1,%2,%3};"
        : "+f"(c[0]), "+f"(c[1]), "+f"(c[2]), "+f"(c[3])
        : "r"(a[0]), "r"(a[1]), "r"(a[2]), "r"(a[3]), "r"(b0), "r"(b1));
}

__device__ __forceinline__ float fast_tanh(float x) {
    float ax = fabsf(x);
    float t;
    asm("ex2.approx.f32 %0, %1;" : "=f"(t) : "f"(ax * -2.885390082f));
    float r = __fdividef(1.f - t, 1.f + t);
    return copysignf(r, x);
}

// ---------------------------------------------------------------- prep kernel
// blocks 0..5375: w*mask transpose tiles (32x32, 4 rows/thread)
// 5376..6399: x conv + ||x||^2 ; 6400..6431: mu ; 6432..6435: zero pad
__global__ void prep_all_kernel(const float* __restrict__ w,
                                const float* __restrict__ m,
                                const float* __restrict__ x,
                                const float* __restrict__ mu) {
    const int tid = threadIdx.x;
    const int bb = blockIdx.x;

    if (bb < NWBLK) {
        __shared__ float s[32][33];
        int n0 = (bb % 336) * 32, k0 = (bb / 336) * 32;
        int tx = tid & 31, ty8 = tid >> 5;
#pragma unroll
        for (int j = 0; j < 4; j++) {
            int ty = ty8 + 8 * j;
            size_t gi = (size_t)(k0 + ty) * LDIM + n0 + tx;
            s[ty][tx] = w[gi] * m[gi];
        }
        __syncthreads();
#pragma unroll
        for (int j = 0; j < 4; j++) {
            int ty = ty8 + 8 * j;
            g_B[(size_t)(n0 + ty) * KDIM + k0 + tx] = __float2half_rn(s[tx][ty]);
        }
        return;
    }

    const int wid = tid >> 5, lane = tid & 31;
    const int mb = bb - NWBLK;
    if (mb < 1024) {
        int row = mb * 8 + wid;
        const float* src = x + (size_t)row * KDIM;
        __half* dst = g_A + (size_t)row * KDIM;
        float sq = 0.f;
#pragma unroll
        for (int j = 0; j < 4; j++) {
            int idx = lane + j * 32;
            float4 v = *(const float4*)(src + idx * 4);
            sq = fmaf(v.x, v.x, sq); sq = fmaf(v.y, v.y, sq);
            sq = fmaf(v.z, v.z, sq); sq = fmaf(v.w, v.w, sq);
            __half2 h0 = __floats2half2_rn(v.x, v.y);
            __half2 h1 = __floats2half2_rn(v.z, v.w);
            *(uint2*)(dst + idx * 4) = make_uint2(*(uint32_t*)&h0, *(uint32_t*)&h1);
        }
#pragma unroll
        for (int off = 16; off > 0; off >>= 1)
            sq += __shfl_xor_sync(0xffffffffu, sq, off);
        if (lane == 0) g_xn[row] = sq;
    } else if (mb < 1056) {
        int f = (mb - 1024) * 8 + wid;
        const float* src = mu + (size_t)f * KDIM;
        __half* dst = g_B + (size_t)(LDIM + f) * KDIM;
        float sq = 0.f;
#pragma unroll
        for (int j = 0; j < 4; j++) {
            int idx = lane + j * 32;
            float4 v = *(const float4*)(src + idx * 4);
            sq = fmaf(v.x, v.x, sq); sq = fmaf(v.y, v.y, sq);
            sq = fmaf(v.z, v.z, sq); sq = fmaf(v.w, v.w, sq);
            __half2 h0 = __floats2half2_rn(v.x, v.y);
            __half2 h1 = __floats2half2_rn(v.z, v.w);
            *(uint2*)(dst + idx * 4) = make_uint2(*(uint32_t*)&h0, *(uint32_t*)&h1);
        }
#pragma unroll
        for (int off = 16; off > 0; off >>= 1)
            sq += __shfl_xor_sync(0xffffffffu, sq, off);
        if (lane == 0) g_mn[f] = sq;
    } else {
        int row = LDIM + FDIM + (mb - 1056) * 8 + wid;   // 11008..11039
        __half* dst = g_B + (size_t)row * KDIM;
#pragma unroll
        for (int j = 0; j < 4; j++) {
            int idx = lane + j * 32;
            *(uint2*)(dst + idx * 4) = make_uint2(0u, 0u);
        }
    }
}

// ---------------------------------------------------------------- fused GEMM
__global__ __launch_bounds__(NTHREADS, 3)
void fused_gemm_dnf_kernel(const float* __restrict__ bias) {
    extern __shared__ char smp[];
    const uint32_t sb = smem_u32(smp);

    const int tid = threadIdx.x;
    const int wid = tid >> 5, lane = tid & 31;
    const int bx = blockIdx.x;   // 0..111 literals, 112..114 mu
    const int by = blockIdx.y;
    const int warp_m = wid & 3;
    const int warp_n = wid >> 2;

    float* sbias = (float*)(smp + SM_BIAS);
    if (tid < BN && bx < NLT) sbias[tid] = bias[bx * BN + tid];

    const __half* Ag = g_A + (size_t)(by * BM) * KDIM;
    const __half* Bg = g_B + (size_t)(bx * BN) * KDIM;

    const int r16 = lane & 15, l4 = lane >> 4;
    int am128[2], a7[2];
#pragma unroll
    for (int t = 0; t < 2; t++) {
        int row = warp_m * 32 + t * 16 + r16;
        am128[t] = row * 128; a7[t] = row & 7;
    }
    int bn128[3], b7[3];
#pragma unroll
    for (int i = 0; i < 3; i++) {
        int n = warp_n * 48 + i * 16 + r16;
        bn128[i] = n * 128; b7[i] = n & 7;
    }

    float c[2][6][4];
#pragma unroll
    for (int t = 0; t < 2; t++)
#pragma unroll
        for (int n = 0; n < 6; n++)
#pragma unroll
            for (int e = 0; e < 4; e++) c[t][n][e] = 0.f;

#define ISSUE(kt)                                                              \
    {                                                                          \
        const uint32_t stA = sb + ((kt) & 1) * STAGE;                          \
        _Pragma("unroll")                                                      \
        for (int j = 0; j < 4; j++) {                                          \
            int idx = tid + NTHREADS * j;                                      \
            int row = idx >> 3, ch = idx & 7;                                  \
            cp16(stA + row * 128 + ((ch ^ (row & 7)) << 4),                    \
                 Ag + (size_t)row * KDIM + (kt) * BK + ch * 8);                \
        }                                                                      \
        _Pragma("unroll")                                                      \
        for (int j = 0; j < 3; j++) {                                          \
            int idx = tid + NTHREADS * j;                                      \
            int row = idx >> 3, ch = idx & 7;                                  \
            cp16(stA + BOFF + row * 128 + ((ch ^ (row & 7)) << 4),             \
                 Bg + (size_t)row * KDIM + (kt) * BK + ch * 8);                \
        }                                                                      \
        CP_COMMIT();                                                           \
    }

    ISSUE(0);

    const int NKT = KDIM / BK;   // 8
#pragma unroll
    for (int kt = 0; kt < NKT; kt++) {
        CP_WAIT(0);
        __syncthreads();
        if (kt + 1 < NKT) ISSUE(kt + 1);

        const uint32_t sA = sb + (kt & 1) * STAGE;
        const uint32_t sB = sA + BOFF;
#pragma unroll
        for (int ks = 0; ks < 4; ks++) {
            uint32_t af[2][4], bf[3][4];
            const int ch = 2 * ks + l4;
#pragma unroll
            for (int t = 0; t < 2; t++)
                ldsm_x4(sA + am128[t] + ((ch ^ a7[t]) << 4), af[t]);
#pragma unroll
            for (int i = 0; i < 3; i++)
                ldsm_x4(sB + bn128[i] + ((ch ^ b7[i]) << 4), bf[i]);
#pragma unroll
            for (int t = 0; t < 2; t++)
#pragma unroll
                for (int i = 0; i < 3; i++) {
                    mma_f16(c[t][2 * i + 0], af[t], bf[i][0], bf[i][2]);
                    mma_f16(c[t][2 * i + 1], af[t], bf[i][1], bf[i][3]);
                }
        }
    }
#undef ISSUE

    __syncthreads();

    const int g = lane >> 2, cc = lane & 3;

    if (bx >= NLT) {
        const int colbase = bx * BN - LDIM;   // 0, 96, 192
        float* dp = g_dot + (size_t)(by * BM) * DPITCH + colbase;
#pragma unroll
        for (int t = 0; t < 2; t++) {
            int row0 = warp_m * 32 + t * 16 + g;
#pragma unroll
            for (int i = 0; i < 3; i++)
#pragma unroll
                for (int j = 0; j < 2; j++) {
                    int colb = warp_n * 48 + i * 16 + j * 8 + 2 * cc;
                    int nt = 2 * i + j;
                    *(float2*)(dp + (size_t)row0 * DPITCH + colb) =
                        make_float2(c[t][nt][0], c[t][nt][1]);
                    *(float2*)(dp + (size_t)(row0 + 8) * DPITCH + colb) =
                        make_float2(c[t][nt][2], c[t][nt][3]);
                }
        }
        return;
    }

    // ---------------- literal epilogue: tanh + conj reduce ----------------
    float* Ls = (float*)smp;   // [128][LPITCH] = 53 KB, fits in 2 stages
#pragma unroll
    for (int t = 0; t < 2; t++) {
        int row0 = warp_m * 32 + t * 16 + g;
#pragma unroll
        for (int i = 0; i < 3; i++)
#pragma unroll
            for (int j = 0; j < 2; j++) {
                int colb = warp_n * 48 + i * 16 + j * 8 + 2 * cc;
                int nt = 2 * i + j;
                float b0 = sbias[colb], b1 = sbias[colb + 1];
                float2 v0, v1;
                v0.x = fast_tanh(c[t][nt][0] + b0);
                v0.y = fast_tanh(c[t][nt][1] + b1);
                v1.x = fast_tanh(c[t][nt][2] + b0);
                v1.y = fast_tanh(c[t][nt][3] + b1);
                *(float2*)(Ls + row0 * LPITCH + colb) = v0;
                *(float2*)(Ls + (row0 + 8) * LPITCH + colb) = v1;
            }
    }
    __syncthreads();

    for (int t = tid; t < BM * 24; t += NTHREADS) {
        int ci  = t % 24;
        int row = t / 24;
        int tri = ci / 3, p = ci % 3;
        int base = tri * 12 + p * (p + 1);   // 0, 2, 6
        int dep  = 2 * (p + 1);              // 2, 4, 6
        const float* rp = Ls + row * LPITCH + base;
        float s = 0.f;
        for (int qq = 0; qq < dep; qq++) s += rp[qq];
        g_conj[(size_t)(by * BM + row) * CDIM + bx * 24 + ci] =
            __float2half_rn(fast_tanh(s - (float)dep + 1.5f));
    }
}

// ---------------------------------------------------------------- finalize
#define RB 16

__device__ __forceinline__ float h2sum(__half2 v) {
    float2 f = __half22float2(v);
    return f.x + f.y;
}

__global__ __launch_bounds__(256)
void finalize_kernel(const float* __restrict__ sigma, float* __restrict__ out)
{
    __shared__ float red[8][RB + 1];
    __shared__ float xns[RB];

    const int tid = threadIdx.x;
    const int f   = tid;
    const int r0  = blockIdx.x * RB;
    const int lane = tid & 31, warp = tid >> 5;

    if (tid < RB) xns[tid] = g_xn[r0 + tid];

    float dt[RB];
#pragma unroll
    for (int r = 0; r < RB; r++) dt[r] = g_dot[(size_t)(r0 + r) * DPITCH + f];

    const float mn    = g_mn[f];
    const float sig   = sigma[f];
    const float inv2s = 0.5f / (sig * sig);
    const int   g     = f >> 6;
    const int   nconj = 6 + 3 * g;
    const int   cstart = 96 * g * (g + 3) + (f & 63) * nconj;
    const int   odd   = cstart & 1;
    __syncthreads();   // xns ready

    float dnnf[RB], ev[RB];
#pragma unroll
    for (int r = 0; r < RB; r++) {
        const __half* cp = g_conj + (size_t)(r0 + r) * CDIM + cstart;
        float s = 0.f;
        if (g == 0) {
            const __half2* p = (const __half2*)cp;
#pragma unroll
            for (int q = 0; q < 3; q++) s += h2sum(__ldg(p + q));
        } else if (g == 2) {
            const __half2* p = (const __half2*)cp;
#pragma unroll
            for (int q = 0; q < 6; q++) s += h2sum(__ldg(p + q));
        } else if (g == 1) {
            const __half2* p = (const __half2*)(cp + odd);
#pragma unroll
            for (int q = 0; q < 4; q++) s += h2sum(__ldg(p + q));
            s += __half2float(__ldg(odd ? cp : cp + 8));
        } else {
            const __half2* p = (const __half2*)(cp + odd);
#pragma unroll
            for (int q = 0; q < 7; q++) s += h2sum(__ldg(p + q));
            s += __half2float(__ldg(odd ? cp : cp + 14));
        }
        dnnf[r] = fast_tanh(s + (float)nconj - 1.5f);

        float sq = xns[r] - 2.f * dt[r] + mn;
        float logit = 2.0f * expf(-sq * inv2s);
        ev[r] = expf(logit);

        float v = ev[r];
#pragma unroll
        for (int off = 16; off > 0; off >>= 1)
            v += __shfl_xor_sync(0xffffffffu, v, off);
        if (lane == 0) red[warp][r] = v;
    }
    __syncthreads();   // single barrier

#pragma unroll
    for (int r = 0; r < RB; r++) {
        float tot = red[0][r] + red[1][r] + red[2][r] + red[3][r] +
                    red[4][r] + red[5][r] + red[6][r] + red[7][r];
        out[(size_t)(r0 + r) * FDIM + f] = dnnf[r] * (ev[r] / tot);
    }
}

// ---------------------------------------------------------------- launch
extern "C" void kernel_launch(void* const* d_in, const int* in_sizes, int n_in,
                              void* d_out, int out_size)
{
    const float* x     = (const float*)d_in[0];
    const float* w     = (const float*)d_in[1];
    const float* msk   = (const float*)d_in[2];
    const float* bias  = (const float*)d_in[3];
    const float* mu    = (const float*)d_in[4];
    const float* sigma = (const float*)d_in[5];
    float* out = (float*)d_out;

    cudaFuncSetAttribute(fused_gemm_dnf_kernel,
                         cudaFuncAttributeMaxDynamicSharedMemorySize, SMEM_NEED);

    prep_all_kernel<<<NWBLK + 1060, 256>>>(w, msk, x, mu);
    {
        dim3 grid(LDIM2 / BN, BATCH / BM);   // (115, 64)
        fused_gemm_dnf_kernel<<<grid, NTHREADS, SMEM_NEED>>>(bias);
    }
    finalize_kernel<<<BATCH / RB, 256>>>(sigma, out);
}

// round 15
// speedup vs baseline: 1.6113x; 1.0840x over previous
#include <cuda_runtime.h>
#include <cuda_fp16.h>
#include <cstdint>

// ----------------------------------------------------------------------------
// B = 8192, K = 512, L = 10752 literals, C = 2688 conj, F = 256
// fp16 mma.sync m16n8k16 GEMM; x@muT folded in as extra N-tiles.
// K-chunked pre-swizzled scratch + cp.async.bulk single-issue pipeline.
// 128x96 CTA, 256 threads, 3 CTAs/SM, 2-stage mbarrier double buffer.
// ----------------------------------------------------------------------------
#define BATCH   8192
#define KDIM    512
#define LDIM    10752
#define LDIM2   11040        // + 256 mu rows + 32 zero pad (115 tiles exactly)
#define CDIM    2688
#define FDIM    256
#define DPITCH  384

#define BM 128
#define BN 96                // 8 triples = 24 conjunctions (triple-aligned)
#define BK 64
#define NKT 8                // 512 / 64
#define NTHREADS 256         // 8 warps: 4 (m) x 2 (n), warp tile 32 x 48
#define AB_BYTES 16384       // A stage: 128 rows x 128 B
#define BB_BYTES 12288       // B stage:  96 rows x 128 B
#define STAGE   28672
#define SM_FULL (2 * STAGE)  // 2 mbarriers @ 57344
#define SM_BIAS (2 * STAGE + 64)
#define SMEM_NEED (SM_BIAS + 448)
#define LPITCH  104
#define NLT     (LDIM / BN)  // 112 literal tiles; bx 112..114 are mu tiles

#define NWBLK   (336 * 16)   // 5376 w-transpose tiles

// K-chunked, pre-swizzled scratch (layout == smem stage layout)
__device__ unsigned char g_A2[(size_t)NKT * BATCH * 128];
__device__ unsigned char g_B2[(size_t)NKT * LDIM2 * 128];
__device__ __half g_conj[(size_t)BATCH * CDIM];
__device__ float g_dot[(size_t)BATCH * DPITCH];
__device__ float g_xn[BATCH];
__device__ float g_mn[FDIM];

// ---------------------------------------------------------------- helpers
__device__ __forceinline__ uint32_t smem_u32(const void* p) {
    uint32_t a;
    asm("{ .reg .u64 t; cvta.to.shared.u64 t, %1; cvt.u32.u64 %0, t; }" : "=r"(a) : "l"(p));
    return a;
}
#define MBARRIER_INIT(a, n) \
    asm volatile("mbarrier.init.shared.b64 [%0], %1;" :: "r"((uint32_t)(a)), "r"((uint32_t)(n)) : "memory")
#define MBARRIER_EXPECT_TX(a, tx) \
    asm volatile("mbarrier.arrive.expect_tx.shared.b64 _, [%0], %1;" :: "r"((uint32_t)(a)), "r"((uint32_t)(tx)) : "memory")
#define MBARRIER_WAIT_PARITY(a, p) do {                                        \
    uint32_t _m = (uint32_t)(a); uint32_t _p = (uint32_t)(p); uint32_t _d;     \
    asm volatile("{\n\t.reg .pred q;\n\t"                                      \
        "mbarrier.try_wait.parity.acquire.cta.shared::cta.b64 q, [%1], %2;\n\t"\
        "selp.b32 %0, 1, 0, q;\n\t}"                                           \
        : "=r"(_d) : "r"(_m), "r"(_p) : "memory");                             \
    if (!_d) {                                                                 \
        asm volatile("{\n\t.reg .pred q;\n\t"                                  \
            "WL_%=:\n\t"                                                       \
            "mbarrier.try_wait.parity.acquire.cta.shared::cta.b64 q, [%0], %1, 0x989680;\n\t" \
            "@q bra.uni WD_%=;\n\t"                                            \
            "bra.uni WL_%=;\n\t"                                               \
            "WD_%=:\n\t}"                                                      \
            :: "r"(_m), "r"(_p) : "memory");                                   \
    }                                                                          \
} while (0)
#define BULK(dst, src, bytes, mbar) \
    asm volatile("cp.async.bulk.shared::cluster.global.mbarrier::complete_tx::bytes [%0], [%1], %2, [%3];" \
        :: "r"((uint32_t)(dst)), "l"(src), "r"((uint32_t)(bytes)), "r"((uint32_t)(mbar)) : "memory")

__device__ __forceinline__ void ldsm_x4(uint32_t addr, uint32_t r[4]) {
    asm volatile("ldmatrix.sync.aligned.m8n8.x4.shared.b16 {%0,%1,%2,%3}, [%4];"
        : "=r"(r[0]), "=r"(r[1]), "=r"(r[2]), "=r"(r[3]) : "r"(addr));
}
__device__ __forceinline__ void mma_f16(float c[4], const uint32_t a[4],
                                        uint32_t b0, uint32_t b1) {
    asm volatile("mma.sync.aligned.m16n8k16.row.col.f32.f16.f16.f32 "
        "{%0,%1,%2,%3}, {%4,%5,%6,%7}, {%8,%9}, {%0,%1,%2,%3};"
        : "+f"(c[0]), "+f"(c[1]), "+f"(c[2]), "+f"(c[3])
        : "r"(a[0]), "r"(a[1]), "r"(a[2]), "r"(a[3]), "r"(b0), "r"(b1));
}

__device__ __forceinline__ float fast_tanh(float x) {
    float ax = fabsf(x);
    float t;
    asm("ex2.approx.f32 %0, %1;" : "=f"(t) : "f"(ax * -2.885390082f));
    float r = __fdividef(1.f - t, 1.f + t);
    return copysignf(r, x);
}

// ---------------------------------------------------------------- prep kernel
// blocks 0..5375: w*mask transpose tiles -> chunked swizzled g_B2
// 5376..6399: x -> chunked swizzled g_A2 + ||x||^2
// 6400..6431: mu -> g_B2 rows LDIM.. ; 6432..6435: zero pad rows
__global__ void prep_all_kernel(const float* __restrict__ w,
                                const float* __restrict__ m,
                                const float* __restrict__ x,
                                const float* __restrict__ mu) {
    const int tid = threadIdx.x;
    const int bb = blockIdx.x;

    if (bb < NWBLK) {
        __shared__ float s[32][33];
        int n0 = (bb % 336) * 32, k0 = (bb / 336) * 32;
        int tx = tid & 31, ty8 = tid >> 5;
#pragma unroll
        for (int j = 0; j < 4; j++) {
            int ty = ty8 + 8 * j;
            size_t gi = (size_t)(k0 + ty) * LDIM + n0 + tx;
            s[ty][tx] = w[gi] * m[gi];
        }
        __syncthreads();
#pragma unroll
        for (int j = 0; j < 4; j++) {
            int ty = ty8 + 8 * j;
            int l = n0 + ty, k = k0 + tx;
            int kt = k >> 6, kk = k & 63;
            size_t off = (size_t)kt * (LDIM2 * 128) + (size_t)l * 128 +
                         ((((kk >> 3) ^ (l & 7)) << 4) | ((kk & 7) * 2));
            *(__half*)(g_B2 + off) = __float2half_rn(s[tx][ty]);
        }
        return;
    }

    const int wid = tid >> 5, lane = tid & 31;
    const int mb = bb - NWBLK;
    if (mb < 1024) {
        int row = mb * 8 + wid;
        const float* src = x + (size_t)row * KDIM;
        float sq = 0.f;
#pragma unroll
        for (int j = 0; j < 4; j++) {
            int idx = lane + j * 32;           // 0..127, 4 floats each
            float4 v = *(const float4*)(src + idx * 4);
            sq = fmaf(v.x, v.x, sq); sq = fmaf(v.y, v.y, sq);
            sq = fmaf(v.z, v.z, sq); sq = fmaf(v.w, v.w, sq);
            __half2 h0 = __floats2half2_rn(v.x, v.y);
            __half2 h1 = __floats2half2_rn(v.z, v.w);
            int kt = idx >> 4, ch = (idx >> 1) & 7, b = (idx & 1) * 8;
            size_t off = (size_t)kt * (BATCH * 128) + (size_t)row * 128 +
                         (((ch ^ (row & 7)) << 4) | b);
            *(uint2*)(g_A2 + off) = make_uint2(*(uint32_t*)&h0, *(uint32_t*)&h1);
        }
#pragma unroll
        for (int off = 16; off > 0; off >>= 1)
            sq += __shfl_xor_sync(0xffffffffu, sq, off);
        if (lane == 0) g_xn[row] = sq;
    } else if (mb < 1056) {
        int f = (mb - 1024) * 8 + wid;
        int l = LDIM + f;
        const float* src = mu + (size_t)f * KDIM;
        float sq = 0.f;
#pragma unroll
        for (int j = 0; j < 4; j++) {
            int idx = lane + j * 32;
            float4 v = *(const float4*)(src + idx * 4);
            sq = fmaf(v.x, v.x, sq); sq = fmaf(v.y, v.y, sq);
            sq = fmaf(v.z, v.z, sq); sq = fmaf(v.w, v.w, sq);
            __half2 h0 = __floats2half2_rn(v.x, v.y);
            __half2 h1 = __floats2half2_rn(v.z, v.w);
            int kt = idx >> 4, ch = (idx >> 1) & 7, b = (idx & 1) * 8;
            size_t off = (size_t)kt * (LDIM2 * 128) + (size_t)l * 128 +
                         (((ch ^ (l & 7)) << 4) | b);
            *(uint2*)(g_B2 + off) = make_uint2(*(uint32_t*)&h0, *(uint32_t*)&h1);
        }
#pragma unroll
        for (int off = 16; off > 0; off >>= 1)
            sq += __shfl_xor_sync(0xffffffffu, sq, off);
        if (lane == 0) g_mn[f] = sq;
    } else {
        int l = LDIM + FDIM + (mb - 1056) * 8 + wid;   // 11008..11039
#pragma unroll
        for (int j = 0; j < 4; j++) {
            int idx = lane + j * 32;
            int kt = idx >> 4;
            size_t off = (size_t)kt * (LDIM2 * 128) + (size_t)l * 128 + ((idx & 15) * 8);
            *(uint2*)(g_B2 + off) = make_uint2(0u, 0u);
        }
    }
}

// ---------------------------------------------------------------- fused GEMM
__global__ __launch_bounds__(NTHREADS, 3)
void fused_gemm_dnf_kernel(const float* __restrict__ bias) {
    extern __shared__ char smp[];
    const uint32_t sb = smem_u32(smp);

    const int tid = threadIdx.x;
    const int wid = tid >> 5, lane = tid & 31;
    const int bx = blockIdx.x;   // 0..111 literals, 112..114 mu
    const int by = blockIdx.y;
    const int warp_m = wid & 3;
    const int warp_n = wid >> 2;

    if (tid == 0) {
        MBARRIER_INIT(sb + SM_FULL, 1);
        MBARRIER_INIT(sb + SM_FULL + 8, 1);
    }
    float* sbias = (float*)(smp + SM_BIAS);
    if (tid < BN && bx < NLT) sbias[tid] = bias[bx * BN + tid];
    __syncthreads();

    const unsigned char* Asrc = g_A2 + (size_t)by * BM * 128;
    const unsigned char* Bsrc = g_B2 + (size_t)bx * BN * 128;

    const int r16 = lane & 15, l4 = lane >> 4;
    int am128[2], a7[2];
#pragma unroll
    for (int t = 0; t < 2; t++) {
        int row = warp_m * 32 + t * 16 + r16;
        am128[t] = row * 128; a7[t] = row & 7;
    }
    int bn128[3], b7[3];
#pragma unroll
    for (int i = 0; i < 3; i++) {
        int n = warp_n * 48 + i * 16 + r16;
        bn128[i] = n * 128; b7[i] = n & 7;
    }

    float c[2][6][4];
#pragma unroll
    for (int t = 0; t < 2; t++)
#pragma unroll
        for (int n = 0; n < 6; n++)
#pragma unroll
            for (int e = 0; e < 4; e++) c[t][n][e] = 0.f;

#define ISSUE(kt)                                                              \
    if (tid == 0) {                                                            \
        const uint32_t mb = sb + SM_FULL + ((kt) & 1) * 8;                     \
        MBARRIER_EXPECT_TX(mb, STAGE);                                         \
        BULK(sb + ((kt) & 1) * STAGE,                                          \
             Asrc + (size_t)(kt) * (BATCH * 128), AB_BYTES, mb);               \
        BULK(sb + ((kt) & 1) * STAGE + AB_BYTES,                               \
             Bsrc + (size_t)(kt) * (LDIM2 * 128), BB_BYTES, mb);               \
    }

    ISSUE(0);

#pragma unroll
    for (int kt = 0; kt < NKT; kt++) {
        if (kt + 1 < NKT) ISSUE(kt + 1);      // other buffer free (synced last iter)
        MBARRIER_WAIT_PARITY(sb + SM_FULL + (kt & 1) * 8, (kt >> 1) & 1);

        const uint32_t sA = sb + (kt & 1) * STAGE;
        const uint32_t sB = sA + AB_BYTES;
#pragma unroll
        for (int ks = 0; ks < 4; ks++) {
            uint32_t af[2][4], bf[3][4];
            const int ch = 2 * ks + l4;
#pragma unroll
            for (int t = 0; t < 2; t++)
                ldsm_x4(sA + am128[t] + ((ch ^ a7[t]) << 4), af[t]);
#pragma unroll
            for (int i = 0; i < 3; i++)
                ldsm_x4(sB + bn128[i] + ((ch ^ b7[i]) << 4), bf[i]);
#pragma unroll
            for (int t = 0; t < 2; t++)
#pragma unroll
                for (int i = 0; i < 3; i++) {
                    mma_f16(c[t][2 * i + 0], af[t], bf[i][0], bf[i][2]);
                    mma_f16(c[t][2 * i + 1], af[t], bf[i][1], bf[i][3]);
                }
        }
        __syncthreads();   // all warps done with this buffer
    }
#undef ISSUE

    const int g = lane >> 2, cc = lane & 3;

    if (bx >= NLT) {
        const int colbase = bx * BN - LDIM;   // 0, 96, 192
        float* dp = g_dot + (size_t)(by * BM) * DPITCH + colbase;
#pragma unroll
        for (int t = 0; t < 2; t++) {
            int row0 = warp_m * 32 + t * 16 + g;
#pragma unroll
            for (int i = 0; i < 3; i++)
#pragma unroll
                for (int j = 0; j < 2; j++) {
                    int colb = warp_n * 48 + i * 16 + j * 8 + 2 * cc;
                    int nt = 2 * i + j;
                    *(float2*)(dp + (size_t)row0 * DPITCH + colb) =
                        make_float2(c[t][nt][0], c[t][nt][1]);
                    *(float2*)(dp + (size_t)(row0 + 8) * DPITCH + colb) =
                        make_float2(c[t][nt][2], c[t][nt][3]);
                }
        }
        return;
    }

    // ---------------- literal epilogue: tanh + conj reduce ----------------
    float* Ls = (float*)smp;   // [128][LPITCH] = 53 KB
#pragma unroll
    for (int t = 0; t < 2; t++) {
        int row0 = warp_m * 32 + t * 16 + g;
#pragma unroll
        for (int i = 0; i < 3; i++)
#pragma unroll
            for (int j = 0; j < 2; j++) {
                int colb = warp_n * 48 + i * 16 + j * 8 + 2 * cc;
                int nt = 2 * i + j;
                float b0 = sbias[colb], b1 = sbias[colb + 1];
                float2 v0, v1;
                v0.x = fast_tanh(c[t][nt][0] + b0);
                v0.y = fast_tanh(c[t][nt][1] + b1);
                v1.x = fast_tanh(c[t][nt][2] + b0);
                v1.y = fast_tanh(c[t][nt][3] + b1);
                *(float2*)(Ls + row0 * LPITCH + colb) = v0;
                *(float2*)(Ls + (row0 + 8) * LPITCH + colb) = v1;
            }
    }
    __syncthreads();

    for (int t = tid; t < BM * 24; t += NTHREADS) {
        int ci  = t % 24;
        int row = t / 24;
        int tri = ci / 3, p = ci % 3;
        int base = tri * 12 + p * (p + 1);   // 0, 2, 6
        int dep  = 2 * (p + 1);              // 2, 4, 6
        const float* rp = Ls + row * LPITCH + base;
        float s = 0.f;
        for (int qq = 0; qq < dep; qq++) s += rp[qq];
        g_conj[(size_t)(by * BM + row) * CDIM + bx * 24 + ci] =
            __float2half_rn(fast_tanh(s - (float)dep + 1.5f));
    }
}

// ---------------------------------------------------------------- finalize
#define RB 16

__device__ __forceinline__ float h2sum(__half2 v) {
    float2 f = __half22float2(v);
    return f.x + f.y;
}

__global__ __launch_bounds__(256)
void finalize_kernel(const float* __restrict__ sigma, float* __restrict__ out)
{
    __shared__ float red[8][RB + 1];
    __shared__ float xns[RB];

    const int tid = threadIdx.x;
    const int f   = tid;
    const int r0  = blockIdx.x * RB;
    const int lane = tid & 31, warp = tid >> 5;

    if (tid < RB) xns[tid] = g_xn[r0 + tid];

    float dt[RB];
#pragma unroll
    for (int r = 0; r < RB; r++) dt[r] = g_dot[(size_t)(r0 + r) * DPITCH + f];

    const float mn    = g_mn[f];
    const float sig   = sigma[f];
    const float inv2s = 0.5f / (sig * sig);
    const int   g     = f >> 6;
    const int   nconj = 6 + 3 * g;
    const int   cstart = 96 * g * (g + 3) + (f & 63) * nconj;
    const int   odd   = cstart & 1;
    __syncthreads();

    float dnnf[RB], ev[RB];
#pragma unroll
    for (int r = 0; r < RB; r++) {
        const __half* cp = g_conj + (size_t)(r0 + r) * CDIM + cstart;
        float s = 0.f;
        if (g == 0) {
            const __half2* p = (const __half2*)cp;
#pragma unroll
            for (int q = 0; q < 3; q++) s += h2sum(__ldg(p + q));
        } else if (g == 2) {
            const __half2* p = (const __half2*)cp;
#pragma unroll
            for (int q = 0; q < 6; q++) s += h2sum(__ldg(p + q));
        } else if (g == 1) {
            const __half2* p = (const __half2*)(cp + odd);
#pragma unroll
            for (int q = 0; q < 4; q++) s += h2sum(__ldg(p + q));
            s += __half2float(__ldg(odd ? cp : cp + 8));
        } else {
            const __half2* p = (const __half2*)(cp + odd);
#pragma unroll
            for (int q = 0; q < 7; q++) s += h2sum(__ldg(p + q));
            s += __half2float(__ldg(odd ? cp : cp + 14));
        }
        dnnf[r] = fast_tanh(s + (float)nconj - 1.5f);

        float sq = xns[r] - 2.f * dt[r] + mn;
        float logit = 2.0f * expf(-sq * inv2s);
        ev[r] = expf(logit);

        float v = ev[r];
#pragma unroll
        for (int off = 16; off > 0; off >>= 1)
            v += __shfl_xor_sync(0xffffffffu, v, off);
        if (lane == 0) red[warp][r] = v;
    }
    __syncthreads();

#pragma unroll
    for (int r = 0; r < RB; r++) {
        float tot = red[0][r] + red[1][r] + red[2][r] + red[3][r] +
                    red[4][r] + red[5][r] + red[6][r] + red[7][r];
        out[(size_t)(r0 + r) * FDIM + f] = dnnf[r] * (ev[r] / tot);
    }
}

// ---------------------------------------------------------------- launch
extern "C" void kernel_launch(void* const* d_in, const int* in_sizes, int n_in,
                              void* d_out, int out_size)
{
    const float* x     = (const float*)d_in[0];
    const float* w     = (const float*)d_in[1];
    const float* msk   = (const float*)d_in[2];
    const float* bias  = (const float*)d_in[3];
    const float* mu    = (const float*)d_in[4];
    const float* sigma = (const float*)d_in[5];
    float* out = (float*)d_out;

    cudaFuncSetAttribute(fused_gemm_dnf_kernel,
                         cudaFuncAttributeMaxDynamicSharedMemorySize, SMEM_NEED);

    prep_all_kernel<<<NWBLK + 1060, 256>>>(w, msk, x, mu);
    {
        dim3 grid(LDIM2 / BN, BATCH / BM);   // (115, 64)
        fused_gemm_dnf_kernel<<<grid, NTHREADS, SMEM_NEED>>>(bias);
    }
    finalize_kernel<<<BATCH / RB, 256>>>(sigma, out);
}

// round 17
// speedup vs baseline: 1.7691x; 1.0979x over previous
#include <cuda_runtime.h>
#include <cuda_fp16.h>
#include <cstdint>

// ----------------------------------------------------------------------------
// B = 8192, K = 512, L = 10752 literals, C = 2688 conj, F = 256
// fp16 mma.sync m16n8k16 GEMM; x@muT folded in as extra N-tiles.
// K-chunked pre-swizzled scratch + cp.async.bulk single-issue pipeline.
// 128x96 CTA, 256 threads, 3 CTAs/SM, 2-stage mbarrier double buffer.
// Pair-sum epilogue (conj boundaries are pair-aligned). PPITCH fixed: 49.
// ----------------------------------------------------------------------------
#define BATCH   8192
#define KDIM    512
#define LDIM    10752
#define LDIM2   11040        // + 256 mu rows + 32 zero pad (115 tiles exactly)
#define CDIM    2688
#define FDIM    256
#define DPITCH  384

#define BM 128
#define BN 96                // 8 triples = 24 conjunctions (triple-aligned)
#define BK 64
#define NKT 8                // 512 / 64
#define NTHREADS 256         // 8 warps: 4 (m) x 2 (n), warp tile 32 x 48
#define AB_BYTES 16384       // A stage: 128 rows x 128 B
#define BB_BYTES 12288       // B stage:  96 rows x 128 B
#define STAGE   28672
#define SM_FULL (2 * STAGE)  // 2 mbarriers @ 57344
#define SM_BIAS (2 * STAGE + 64)
#define SMEM_NEED (SM_BIAS + 448)
#define PPITCH  49           // 48 pairs per 96-col row + 1 pad
#define NLT     (LDIM / BN)  // 112 literal tiles; bx 112..114 are mu tiles

#define NWBLK   (336 * 16)   // 5376 w-transpose tiles

// K-chunked, pre-swizzled scratch (layout == smem stage layout)
__device__ unsigned char g_A2[(size_t)NKT * BATCH * 128];
__device__ unsigned char g_B2[(size_t)NKT * LDIM2 * 128];
__device__ __half g_conj[(size_t)BATCH * CDIM];
__device__ float g_dot[(size_t)BATCH * DPITCH];
__device__ float g_xn[BATCH];
__device__ float g_mn[FDIM];

// ---------------------------------------------------------------- helpers
__device__ __forceinline__ uint32_t smem_u32(const void* p) {
    uint32_t a;
    asm("{ .reg .u64 t; cvta.to.shared.u64 t, %1; cvt.u32.u64 %0, t; }" : "=r"(a) : "l"(p));
    return a;
}
#define MBARRIER_INIT(a, n) \
    asm volatile("mbarrier.init.shared.b64 [%0], %1;" :: "r"((uint32_t)(a)), "r"((uint32_t)(n)) : "memory")
#define MBARRIER_EXPECT_TX(a, tx) \
    asm volatile("mbarrier.arrive.expect_tx.shared.b64 _, [%0], %1;" :: "r"((uint32_t)(a)), "r"((uint32_t)(tx)) : "memory")
#define MBARRIER_WAIT_PARITY(a, p) do {                                        \
    uint32_t _m = (uint32_t)(a); uint32_t _p = (uint32_t)(p); uint32_t _d;     \
    asm volatile("{\n\t.reg .pred q;\n\t"                                      \
        "mbarrier.try_wait.parity.acquire.cta.shared::cta.b64 q, [%1], %2;\n\t"\
        "selp.b32 %0, 1, 0, q;\n\t}"                                           \
        : "=r"(_d) : "r"(_m), "r"(_p) : "memory");                             \
    if (!_d) {                                                                 \
        asm volatile("{\n\t.reg .pred q;\n\t"                                  \
            "WL_%=:\n\t"                                                       \
            "mbarrier.try_wait.parity.acquire.cta.shared::cta.b64 q, [%0], %1, 0x989680;\n\t" \
            "@q bra.uni WD_%=;\n\t"                                            \
            "bra.uni WL_%=;\n\t"                                               \
            "WD_%=:\n\t}"                                                      \
            :: "r"(_m), "r"(_p) : "memory");                                   \
    }                                                                          \
} while (0)
#define BULK(dst, src, bytes, mbar) \
    asm volatile("cp.async.bulk.shared::cluster.global.mbarrier::complete_tx::bytes [%0], [%1], %2, [%3];" \
        :: "r"((uint32_t)(dst)), "l"(src), "r"((uint32_t)(bytes)), "r"((uint32_t)(mbar)) : "memory")

__device__ __forceinline__ void ldsm_x4(uint32_t addr, uint32_t r[4]) {
    asm volatile("ldmatrix.sync.aligned.m8n8.x4.shared.b16 {%0,%1,%2,%3}, [%4];"
        : "=r"(r[0]), "=r"(r[1]), "=r"(r[2]), "=r"(r[3]) : "r"(addr));
}
__device__ __forceinline__ void mma_f16(float c[4], const uint32_t a[4],
                                        uint32_t b0, uint32_t b1) {
    asm volatile("mma.sync.aligned.m16n8k16.row.col.f32.f16.f16.f32 "
        "{%0,%1,%2,%3}, {%4,%5,%6,%7}, {%8,%9}, {%0,%1,%2,%3};"
        : "+f"(c[0]), "+f"(c[1]), "+f"(c[2]), "+f"(c[3])
        : "r"(a[0]), "r"(a[1]), "r"(a[2]), "r"(a[3]), "r"(b0), "r"(b1));
}

__device__ __forceinline__ float fast_tanh(float x) {
    float ax = fabsf(x);
    float t;
    asm("ex2.approx.f32 %0, %1;" : "=f"(t) : "f"(ax * -2.885390082f));
    float r = __fdividef(1.f - t, 1.f + t);
    return copysignf(r, x);
}

// ---------------------------------------------------------------- prep kernel
__global__ void prep_all_kernel(const float* __restrict__ w,
                                const float* __restrict__ m,
                                const float* __restrict__ x,
                                const float* __restrict__ mu) {
    const int tid = threadIdx.x;
    const int bb = blockIdx.x;

    if (bb < NWBLK) {
        __shared__ float s[32][33];
        int n0 = (bb % 336) * 32, k0 = (bb / 336) * 32;
        int tx = tid & 31, ty8 = tid >> 5;
#pragma unroll
        for (int j = 0; j < 4; j++) {
            int ty = ty8 + 8 * j;
            size_t gi = (size_t)(k0 + ty) * LDIM + n0 + tx;
            s[ty][tx] = w[gi] * m[gi];
        }
        __syncthreads();
#pragma unroll
        for (int j = 0; j < 4; j++) {
            int ty = ty8 + 8 * j;
            int l = n0 + ty, k = k0 + tx;
            int kt = k >> 6, kk = k & 63;
            size_t off = (size_t)kt * (LDIM2 * 128) + (size_t)l * 128 +
                         ((((kk >> 3) ^ (l & 7)) << 4) | ((kk & 7) * 2));
            *(__half*)(g_B2 + off) = __float2half_rn(s[tx][ty]);
        }
        return;
    }

    const int wid = tid >> 5, lane = tid & 31;
    const int mb = bb - NWBLK;
    if (mb < 1024) {
        int row = mb * 8 + wid;
        const float* src = x + (size_t)row * KDIM;
        float sq = 0.f;
#pragma unroll
        for (int j = 0; j < 4; j++) {
            int idx = lane + j * 32;
            float4 v = *(const float4*)(src + idx * 4);
            sq = fmaf(v.x, v.x, sq); sq = fmaf(v.y, v.y, sq);
            sq = fmaf(v.z, v.z, sq); sq = fmaf(v.w, v.w, sq);
            __half2 h0 = __floats2half2_rn(v.x, v.y);
            __half2 h1 = __floats2half2_rn(v.z, v.w);
            int kt = idx >> 4, ch = (idx >> 1) & 7, b = (idx & 1) * 8;
            size_t off = (size_t)kt * (BATCH * 128) + (size_t)row * 128 +
                         (((ch ^ (row & 7)) << 4) | b);
            *(uint2*)(g_A2 + off) = make_uint2(*(uint32_t*)&h0, *(uint32_t*)&h1);
        }
#pragma unroll
        for (int off = 16; off > 0; off >>= 1)
            sq += __shfl_xor_sync(0xffffffffu, sq, off);
        if (lane == 0) g_xn[row] = sq;
    } else if (mb < 1056) {
        int f = (mb - 1024) * 8 + wid;
        int l = LDIM + f;
        const float* src = mu + (size_t)f * KDIM;
        float sq = 0.f;
#pragma unroll
        for (int j = 0; j < 4; j++) {
            int idx = lane + j * 32;
            float4 v = *(const float4*)(src + idx * 4);
            sq = fmaf(v.x, v.x, sq); sq = fmaf(v.y, v.y, sq);
            sq = fmaf(v.z, v.z, sq); sq = fmaf(v.w, v.w, sq);
            __half2 h0 = __floats2half2_rn(v.x, v.y);
            __half2 h1 = __floats2half2_rn(v.z, v.w);
            int kt = idx >> 4, ch = (idx >> 1) & 7, b = (idx & 1) * 8;
            size_t off = (size_t)kt * (LDIM2 * 128) + (size_t)l * 128 +
                         (((ch ^ (l & 7)) << 4) | b);
            *(uint2*)(g_B2 + off) = make_uint2(*(uint32_t*)&h0, *(uint32_t*)&h1);
        }
#pragma unroll
        for (int off = 16; off > 0; off >>= 1)
            sq += __shfl_xor_sync(0xffffffffu, sq, off);
        if (lane == 0) g_mn[f] = sq;
    } else {
        int l = LDIM + FDIM + (mb - 1056) * 8 + wid;   // 11008..11039
#pragma unroll
        for (int j = 0; j < 4; j++) {
            int idx = lane + j * 32;
            int kt = idx >> 4;
            size_t off = (size_t)kt * (LDIM2 * 128) + (size_t)l * 128 + ((idx & 15) * 8);
            *(uint2*)(g_B2 + off) = make_uint2(0u, 0u);
        }
    }
}

// ---------------------------------------------------------------- fused GEMM
__global__ __launch_bounds__(NTHREADS, 3)
void fused_gemm_dnf_kernel(const float* __restrict__ bias) {
    extern __shared__ char smp[];
    const uint32_t sb = smem_u32(smp);

    const int tid = threadIdx.x;
    const int wid = tid >> 5, lane = tid & 31;
    const int bx = blockIdx.x;   // 0..111 literals, 112..114 mu
    const int by = blockIdx.y;
    const int warp_m = wid & 3;
    const int warp_n = wid >> 2;

    if (tid == 0) {
        MBARRIER_INIT(sb + SM_FULL, 1);
        MBARRIER_INIT(sb + SM_FULL + 8, 1);
    }
    float* sbias = (float*)(smp + SM_BIAS);
    if (tid < BN && bx < NLT) sbias[tid] = bias[bx * BN + tid];
    __syncthreads();

    const unsigned char* Asrc = g_A2 + (size_t)by * BM * 128;
    const unsigned char* Bsrc = g_B2 + (size_t)bx * BN * 128;

    const int r16 = lane & 15, l4 = lane >> 4;
    int am128[2], a7[2];
#pragma unroll
    for (int t = 0; t < 2; t++) {
        int row = warp_m * 32 + t * 16 + r16;
        am128[t] = row * 128; a7[t] = row & 7;
    }
    int bn128[3], b7[3];
#pragma unroll
    for (int i = 0; i < 3; i++) {
        int n = warp_n * 48 + i * 16 + r16;
        bn128[i] = n * 128; b7[i] = n & 7;
    }

    float c[2][6][4];
#pragma unroll
    for (int t = 0; t < 2; t++)
#pragma unroll
        for (int n = 0; n < 6; n++)
#pragma unroll
            for (int e = 0; e < 4; e++) c[t][n][e] = 0.f;

#define ISSUE(kt)                                                              \
    if (tid == 0) {                                                            \
        const uint32_t mb = sb + SM_FULL + ((kt) & 1) * 8;                     \
        MBARRIER_EXPECT_TX(mb, STAGE);                                         \
        BULK(sb + ((kt) & 1) * STAGE,                                          \
             Asrc + (size_t)(kt) * (BATCH * 128), AB_BYTES, mb);               \
        BULK(sb + ((kt) & 1) * STAGE + AB_BYTES,                               \
             Bsrc + (size_t)(kt) * (LDIM2 * 128), BB_BYTES, mb);               \
    }

    ISSUE(0);

#pragma unroll
    for (int kt = 0; kt < NKT; kt++) {
        if (kt + 1 < NKT) ISSUE(kt + 1);
        MBARRIER_WAIT_PARITY(sb + SM_FULL + (kt & 1) * 8, (kt >> 1) & 1);

        const uint32_t sA = sb + (kt & 1) * STAGE;
        const uint32_t sB = sA + AB_BYTES;
#pragma unroll
        for (int ks = 0; ks < 4; ks++) {
            uint32_t af[2][4], bf[3][4];
            const int ch = 2 * ks + l4;
#pragma unroll
            for (int t = 0; t < 2; t++)
                ldsm_x4(sA + am128[t] + ((ch ^ a7[t]) << 4), af[t]);
#pragma unroll
            for (int i = 0; i < 3; i++)
                ldsm_x4(sB + bn128[i] + ((ch ^ b7[i]) << 4), bf[i]);
#pragma unroll
            for (int t = 0; t < 2; t++)
#pragma unroll
                for (int i = 0; i < 3; i++) {
                    mma_f16(c[t][2 * i + 0], af[t], bf[i][0], bf[i][2]);
                    mma_f16(c[t][2 * i + 1], af[t], bf[i][1], bf[i][3]);
                }
        }
        __syncthreads();
    }
#undef ISSUE

    const int g = lane >> 2, cc = lane & 3;

    if (bx >= NLT) {
        const int colbase = bx * BN - LDIM;   // 0, 96, 192
        float* dp = g_dot + (size_t)(by * BM) * DPITCH + colbase;
#pragma unroll
        for (int t = 0; t < 2; t++) {
            int row0 = warp_m * 32 + t * 16 + g;
#pragma unroll
            for (int i = 0; i < 3; i++)
#pragma unroll
                for (int j = 0; j < 2; j++) {
                    int colb = warp_n * 48 + i * 16 + j * 8 + 2 * cc;
                    int nt = 2 * i + j;
                    *(float2*)(dp + (size_t)row0 * DPITCH + colb) =
                        make_float2(c[t][nt][0], c[t][nt][1]);
                    *(float2*)(dp + (size_t)(row0 + 8) * DPITCH + colb) =
                        make_float2(c[t][nt][2], c[t][nt][3]);
                }
        }
        return;
    }

    // -------- literal epilogue: tanh + PAIR-SUM stage + conj reduce --------
    // Pair boundaries align with conj boundaries: triple = pairs {0 | 1,2 | 3,4,5}.
    float* Ps = (float*)smp;   // [128][PPITCH] pair sums, 25 KB
#pragma unroll
    for (int t = 0; t < 2; t++) {
        int row0 = warp_m * 32 + t * 16 + g;
#pragma unroll
        for (int i = 0; i < 3; i++)
#pragma unroll
            for (int j = 0; j < 2; j++) {
                int colb = warp_n * 48 + i * 16 + j * 8 + 2 * cc;
                int pidx = warp_n * 24 + i * 8 + j * 4 + cc;
                int nt = 2 * i + j;
                float b0 = sbias[colb], b1 = sbias[colb + 1];
                Ps[row0 * PPITCH + pidx] =
                    fast_tanh(c[t][nt][0] + b0) + fast_tanh(c[t][nt][1] + b1);
                Ps[(row0 + 8) * PPITCH + pidx] =
                    fast_tanh(c[t][nt][2] + b0) + fast_tanh(c[t][nt][3] + b1);
            }
    }
    __syncthreads();

    // 128 rows x 24 conj; conj (tri,p) sums pairs tri*6 + {0 | 1,2 | 3,4,5}
    for (int t = tid; t < BM * 24; t += NTHREADS) {
        int ci  = t % 24;
        int row = t / 24;
        int tri = ci / 3, p = ci % 3;
        int pb  = tri * 6 + ((p * (p + 1)) >> 1);   // 0, 1, 3
        const float* rp = Ps + row * PPITCH + pb;
        float s = rp[0];
        if (p > 0) s += rp[1];
        if (p > 1) s += rp[2];
        float dep = 2.f * (p + 1);
        g_conj[(size_t)(by * BM + row) * CDIM + bx * 24 + ci] =
            __float2half_rn(fast_tanh(s - dep + 1.5f));
    }
}

// ---------------------------------------------------------------- finalize
#define RB 16

__device__ __forceinline__ float h2sum(__half2 v) {
    float2 f = __half22float2(v);
    return f.x + f.y;
}

__global__ __launch_bounds__(256)
void finalize_kernel(const float* __restrict__ sigma, float* __restrict__ out)
{
    __shared__ float red[8][RB + 1];
    __shared__ float xns[RB];

    const int tid = threadIdx.x;
    const int f   = tid;
    const int r0  = blockIdx.x * RB;
    const int lane = tid & 31, warp = tid >> 5;

    if (tid < RB) xns[tid] = g_xn[r0 + tid];

    float dt[RB];
#pragma unroll
    for (int r = 0; r < RB; r++) dt[r] = g_dot[(size_t)(r0 + r) * DPITCH + f];

    const float mn    = g_mn[f];
    const float sig   = sigma[f];
    const float inv2s = 0.5f / (sig * sig);
    const int   g     = f >> 6;
    const int   nconj = 6 + 3 * g;
    const int   cstart = 96 * g * (g + 3) + (f & 63) * nconj;
    const int   odd   = cstart & 1;
    __syncthreads();

    float dnnf[RB], ev[RB];
#pragma unroll
    for (int r = 0; r < RB; r++) {
        const __half* cp = g_conj + (size_t)(r0 + r) * CDIM + cstart;
        float s = 0.f;
        if (g == 0) {
            const __half2* p = (const __half2*)cp;
#pragma unroll
            for (int q = 0; q < 3; q++) s += h2sum(__ldg(p + q));
        } else if (g == 2) {
            const __half2* p = (const __half2*)cp;
#pragma unroll
            for (int q = 0; q < 6; q++) s += h2sum(__ldg(p + q));
        } else if (g == 1) {
            const __half2* p = (const __half2*)(cp + odd);
#pragma unroll
            for (int q = 0; q < 4; q++) s += h2sum(__ldg(p + q));
            s += __half2float(__ldg(odd ? cp : cp + 8));
        } else {
            const __half2* p = (const __half2*)(cp + odd);
#pragma unroll
            for (int q = 0; q < 7; q++) s += h2sum(__ldg(p + q));
            s += __half2float(__ldg(odd ? cp : cp + 14));
        }
        dnnf[r] = fast_tanh(s + (float)nconj - 1.5f);

        float sq = xns[r] - 2.f * dt[r] + mn;
        float logit = 2.0f * expf(-sq * inv2s);
        ev[r] = expf(logit);

        float v = ev[r];
#pragma unroll
        for (int off = 16; off > 0; off >>= 1)
            v += __shfl_xor_sync(0xffffffffu, v, off);
        if (lane == 0) red[warp][r] = v;
    }
    __syncthreads();

#pragma unroll
    for (int r = 0; r < RB; r++) {
        float tot = red[0][r] + red[1][r] + red[2][r] + red[3][r] +
                    red[4][r] + red[5][r] + red[6][r] + red[7][r];
        out[(size_t)(r0 + r) * FDIM + f] = dnnf[r] * (ev[r] / tot);
    }
}

// ---------------------------------------------------------------- launch
extern "C" void kernel_launch(void* const* d_in, const int* in_sizes, int n_in,
                              void* d_out, int out_size)
{
    const float* x     = (const float*)d_in[0];
    const float* w     = (const float*)d_in[1];
    const float* msk   = (const float*)d_in[2];
    const float* bias  = (const float*)d_in[3];
    const float* mu    = (const float*)d_in[4];
    const float* sigma = (const float*)d_in[5];
    float* out = (float*)d_out;

    cudaFuncSetAttribute(fused_gemm_dnf_kernel,
                         cudaFuncAttributeMaxDynamicSharedMemorySize, SMEM_NEED);

    prep_all_kernel<<<NWBLK + 1060, 256>>>(w, msk, x, mu);
    {
        dim3 grid(LDIM2 / BN, BATCH / BM);   // (115, 64)
        fused_gemm_dnf_kernel<<<grid, NTHREADS, SMEM_NEED>>>(bias);
    }
    finalize_kernel<<<BATCH / RB, 256>>>(sigma, out);
}